// round 7
// baseline (speedup 1.0000x reference)
#include <cuda_runtime.h>
#include <cuda_bf16.h>
#include <cstdint>
typedef unsigned long long u64;
typedef unsigned int u32;

#define NRAYS 8192
#define SSAMP 128
#define P_DIST 0.55f
#define CUBE_EPS 1e-6f
#define FDE 2e-3f

__device__ float g_val[NRAYS * SSAMP];
__device__ float g_a[NRAYS];
__device__ float g_b[NRAYS];
// [layer][hi/lo]: 16 chunks x 8192B; chunk = 32 n-tiles x 2 k-tiles x (8x8 bf16 =128B)
__device__ __align__(128) unsigned char g_WB[2][2][131072];

// ---- helpers ----
__device__ __forceinline__ u32 smem_u32(const void* p){ return (u32)__cvta_generic_to_shared(p); }
__device__ __forceinline__ float softplusf(float x){ return fmaxf(x,0.f)+log1pf(expf(-fabsf(x))); }
__device__ __forceinline__ float secantf(float dl,float fl,float dh,float fh){
    float den=fh-fl; if(fabsf(den)<1e-12f) den=1e-12f; return -fl*(dh-dl)/den+dl; }
__device__ __forceinline__ u64 pack_dup(float x){ u64 r; asm("mov.b64 %0,{%1,%2};":"=l"(r):"f"(x),"f"(x)); return r; }
__device__ __forceinline__ float2 unpack2(u64 v){ float2 f; asm("mov.b64 {%0,%1},%2;":"=f"(f.x),"=f"(f.y):"l"(v)); return f; }
__device__ __forceinline__ u64 ffma2(u64 a,u64 b,u64 c){ u64 d; asm("fma.rn.f32x2 %0,%1,%2,%3;":"=l"(d):"l"(a),"l"(b),"l"(c)); return d; }
__device__ __forceinline__ void cp16(u32 dst,const void* src){ asm volatile("cp.async.cg.shared.global [%0],[%1],16;"::"r"(dst),"l"(src):"memory"); }
__device__ __forceinline__ void cp_commit(){ asm volatile("cp.async.commit_group;":::"memory"); }
__device__ __forceinline__ void cp_wait0(){ asm volatile("cp.async.wait_group 0;":::"memory"); }
__device__ __forceinline__ void cp_wait1(){ asm volatile("cp.async.wait_group 1;":::"memory"); }

__device__ __forceinline__ void ldm4(u32* r,u32 a){
    asm volatile("ldmatrix.sync.aligned.m8n8.x4.shared.b16 {%0,%1,%2,%3},[%4];"
        :"=r"(r[0]),"=r"(r[1]),"=r"(r[2]),"=r"(r[3]):"r"(a)); }
__device__ __forceinline__ void mma16816(float* d,const u32* a,u32 b0,u32 b1){
    asm volatile("mma.sync.aligned.m16n8k16.row.col.f32.bf16.bf16.f32 "
        "{%0,%1,%2,%3},{%4,%5,%6,%7},{%8,%9},{%0,%1,%2,%3};"
        :"+f"(d[0]),"+f"(d[1]),"+f"(d[2]),"+f"(d[3])
        :"r"(a[0]),"r"(a[1]),"r"(a[2]),"r"(a[3]),"r"(b0),"r"(b1)); }
__device__ __forceinline__ void splitpk(float x,float y,u32&h,u32&l){
    __nv_bfloat16 hx=__float2bfloat16_rn(x), hy=__float2bfloat16_rn(y);
    __nv_bfloat16 lx=__float2bfloat16_rn(x-__bfloat162float(hx));
    __nv_bfloat16 ly=__float2bfloat16_rn(y-__bfloat162float(hy));
    h=((u32)*(unsigned short*)&hx)|(((u32)*(unsigned short*)&hy)<<16);
    l=((u32)*(unsigned short*)&lx)|(((u32)*(unsigned short*)&ly)<<16);
}

// ---- k_prep: W[k][n] fp32 -> tiled bf16 hi/lo blobs ----
__global__ void k_prep(const float* __restrict__ W2,const float* __restrict__ W3){
    int idx=blockIdx.x*blockDim.x+threadIdx.x;
    int layer=idx>>16, e=idx&65535;
    const float* W=layer?W3:W2;
    int k=e>>8, n=e&255;
    float w=W[e];
    __nv_bfloat16 hi=__float2bfloat16_rn(w);
    __nv_bfloat16 lo=__float2bfloat16_rn(w-__bfloat162float(hi));
    int c=k>>4, kt=(k&15)>>3;
    size_t off=(size_t)c*8192+(size_t)(((n>>3)*2+kt)*128)+(size_t)((n&7)*16)+(size_t)((k&7)*2);
    *(__nv_bfloat16*)(g_WB[layer][0]+off)=hi;
    *(__nv_bfloat16*)(g_WB[layer][1]+off)=lo;
}

// ---- cube intersection ----
__global__ void k_setup(const float* __restrict__ ray0,const float* __restrict__ rdir){
    int r=blockIdx.x*blockDim.x+threadIdx.x; if(r>=NRAYS) return;
    float o0=ray0[3*r],o1=ray0[3*r+1],o2=ray0[3*r+2];
    float r0=rdir[3*r],r1=rdir[3*r+1],r2=rdir[3*r+2];
    float ov[3]={o0,o1,o2},rv[3]={r0,r1,r2},t2[2]={0.f,0.f};
    int cnt=0; float rn=sqrtf(r0*r0+r1*r1+r2*r2);
#pragma unroll
    for(int i=0;i<6;i++){
        int ax=i%3; float pv=(i<3)?P_DIST:-P_DIST;
        float den=rv[ax]; if(fabsf(den)<1e-9f) den=1e-9f;
        float t=(pv-ov[ax])/den;
        float q0=o0+t*r0,q1=o1+t*r1,q2=o2+t*r2;
        bool ins=(fabsf(q0)<=P_DIST+CUBE_EPS)&&(fabsf(q1)<=P_DIST+CUBE_EPS)&&(fabsf(q2)<=P_DIST+CUBE_EPS);
        if(ins){ if(cnt<2){ float e0=q0-o0,e1=q1-o1,e2=q2-o2;
                t2[cnt]=sqrtf(e0*e0+e1*e1+e2*e2)/rn; } cnt++; }
    }
    float a,b;
    if(cnt==2){ float lo=fminf(t2[0],t2[1]),hi=fmaxf(t2[0],t2[1]); a=lo; b=(hi-lo)*(1.f/127.f); }
    else { a=0.f; b=2.4f/127.f; }
    g_a[r]=a; g_b[r]=b;
}

// ---- k_big: 64 samples per CTA (2 CTAs per ray), 2 CTAs/SM ----
// smem: A_hi 32K @0, A_lo 32K @32768, Bbuf 2x16384 @65536  (total 98304)
#define ABH 0
#define ABL 32768
#define BBF 65536
__device__ __forceinline__ void stageB(char* dst,const unsigned char* sH,const unsigned char* sL,int tid){
    u32 d=smem_u32(dst);
#pragma unroll
    for(int j=0;j<2;j++){ int u=tid+j*256; cp16(d+u*16,sH+u*16); }
#pragma unroll
    for(int j=0;j<2;j++){ int u=tid+j*256; cp16(d+8192+u*16,sL+u*16); }
}

__global__ void __launch_bounds__(256,2)
k_big(const float* __restrict__ ray0,const float* __restrict__ rdir,
      const float* __restrict__ W1,const float* __restrict__ b1,
      const float* __restrict__ b2,const float* __restrict__ b3,
      const float* __restrict__ W4,const float* __restrict__ b4){
    extern __shared__ char sm[];
    __shared__ float s_bias[256], s_w4[256], s_red[256];
    int tid=threadIdx.x, lane=tid&31, warp=tid>>5;
    int ray=blockIdx.x>>1, half=blockIdx.x&1;
    u32 smb=smem_u32(sm);

    // layer 1 -> A planes (64 m x 256 k)
    float a=g_a[ray], st=g_b[ray];
    float ox=ray0[ray*3],oy=ray0[ray*3+1],oz=ray0[ray*3+2];
    float dx=rdir[ray*3],dy=rdir[ray*3+1],dz=rdir[ray*3+2];
    {
        int m=tid&63, kg=tid>>6;
        int sidx=half*64+m;
        float d=a+(float)sidx*st;
        float px=ox+d*dx,py=oy+d*dy,pz=oz+d*dz;
#pragma unroll 4
        for(int j=0;j<64;j+=2){
            int k=kg*64+j;
            float z0=fmaf(px,W1[k],fmaf(py,W1[256+k],fmaf(pz,W1[512+k],b1[k])));
            float z1=fmaf(px,W1[k+1],fmaf(py,W1[257+k],fmaf(pz,W1[513+k],b1[k+1])));
            float v0=softplusf(z0), v1=softplusf(z1);
            u32 h,l; splitpk(v0,v1,h,l);
            int off=m*512+((((k>>3))^(m&7))<<4)+((k&7)<<1);
            *(u32*)(sm+ABH+off)=h;
            *(u32*)(sm+ABL+off)=l;
        }
    }

    int g2=lane>>3, row=lane&7;
    int mw=warp&1, nw=warp>>1;
    int m0=mw*32, n0=nw*64;
    u32 arow=(u32)((m0+(g2&1)*8+row)*512);
    u32 bl_off=(u32)(n0*32+g2*128+row*16);

    for(int L=0;L<2;L++){
        s_bias[tid]=L?b3[tid]:b2[tid];
        if(L) s_w4[tid]=W4[tid];
        const unsigned char* blobH=g_WB[L][0];
        const unsigned char* blobL=g_WB[L][1];
        float acc[2][8][4];
#pragma unroll
        for(int i=0;i<2;i++)
#pragma unroll
            for(int j=0;j<8;j++){ acc[i][j][0]=0.f; acc[i][j][1]=0.f; acc[i][j][2]=0.f; acc[i][j][3]=0.f; }
        stageB(sm+BBF,blobH,blobL,tid); cp_commit();
        for(int c=0;c<16;c++){
            cp_wait0();
            __syncthreads();
            if(c<15){ stageB(sm+BBF+((c+1)&1)*16384,blobH+(c+1)*8192,blobL+(c+1)*8192,tid); cp_commit(); }
            u32 bb=smb+BBF+(c&1)*16384;
            u32 au=(u32)(((2*c+(g2>>1))^row)<<4);
            u32 ah[2][4], al[2][4];
            ldm4(ah[0],smb+ABH+arow+au);
            ldm4(al[0],smb+ABL+arow+au);
            ldm4(ah[1],smb+ABH+arow+8192u+au);
            ldm4(al[1],smb+ABL+arow+8192u+au);
#pragma unroll
            for(int j=0;j<4;j++){
                u32 ba=bb+bl_off+(u32)(j*512);
                u32 bh[4], bl2[4];
                ldm4(bh,ba);
                ldm4(bl2,ba+8192u);
#pragma unroll
                for(int p=0;p<3;p++){
                    const u32* B=(p==1)?bl2:bh;
#pragma unroll
                    for(int mt=0;mt<2;mt++){
                        const u32* A=(p==2)?al[mt]:ah[mt];
                        mma16816(acc[mt][2*j],A,B[0],B[1]);
                        mma16816(acc[mt][2*j+1],A,B[2],B[3]);
                    }
                }
            }
        }
        __syncthreads();
        if(L==0){
#pragma unroll
            for(int mt=0;mt<2;mt++){
                int r0=m0+mt*16+(lane>>2), r1=r0+8;
#pragma unroll
                for(int nt=0;nt<8;nt++){
                    int n=n0+nt*8+(lane&3)*2;
                    float v0=softplusf(acc[mt][nt][0]+s_bias[n]);
                    float v1=softplusf(acc[mt][nt][1]+s_bias[n+1]);
                    float v2=softplusf(acc[mt][nt][2]+s_bias[n]);
                    float v3=softplusf(acc[mt][nt][3]+s_bias[n+1]);
                    u32 h0,l0,h1,l1;
                    splitpk(v0,v1,h0,l0);
                    splitpk(v2,v3,h1,l1);
                    int o0=r0*512+(((n>>3)^(r0&7))<<4)+(n&7)*2;
                    int o1=r1*512+(((n>>3)^(r1&7))<<4)+(n&7)*2;
                    *(u32*)(sm+ABH+o0)=h0; *(u32*)(sm+ABL+o0)=l0;
                    *(u32*)(sm+ABH+o1)=h1; *(u32*)(sm+ABL+o1)=l1;
                }
            }
        } else {
#pragma unroll
            for(int mt=0;mt<2;mt++){
                float s0=0.f,s1=0.f;
#pragma unroll
                for(int nt=0;nt<8;nt++){
                    int n=n0+nt*8+(lane&3)*2;
                    s0+=softplusf(acc[mt][nt][0]+s_bias[n])*s_w4[n]
                       +softplusf(acc[mt][nt][1]+s_bias[n+1])*s_w4[n+1];
                    s1+=softplusf(acc[mt][nt][2]+s_bias[n])*s_w4[n]
                       +softplusf(acc[mt][nt][3]+s_bias[n+1])*s_w4[n+1];
                }
                s0+=__shfl_xor_sync(0xffffffffu,s0,1); s0+=__shfl_xor_sync(0xffffffffu,s0,2);
                s1+=__shfl_xor_sync(0xffffffffu,s1,1); s1+=__shfl_xor_sync(0xffffffffu,s1,2);
                if((lane&3)==0){
                    int r0=m0+mt*16+(lane>>2);
                    s_red[r0*4+nw]=s0;
                    s_red[(r0+8)*4+nw]=s1;
                }
            }
            __syncthreads();
            if(tid<64)
                g_val[ray*SSAMP+half*64+tid]=s_red[tid*4]+s_red[tid*4+1]+s_red[tid*4+2]+s_red[tid*4+3]+b4[0];
        }
        __syncthreads();
    }
}

// ======== exact-fp32 FFMA machinery for refinement (proven) ========
__device__ __forceinline__ int SWZ(int k,int m){ return (k<<6)+(m^(((k>>3)&7)<<3)); }
__device__ __forceinline__ void stage_chunk(float* wdst,const float* __restrict__ Wsrc,int tid){
    u32 d=smem_u32(wdst)+(u32)tid*16u; const float* s=Wsrc+tid*4;
#pragma unroll
    for(int j=0;j<8;j++) cp16(d+(u32)j*4096u,s+j*1024);
}
__device__ __forceinline__ void gemm_layer(const float* actIn,const float* __restrict__ Wg,
        const float* __restrict__ bias,float* actOut,float* wbuf,int tid){
    const int m0=(tid>>5)<<3, n0=(tid&31)<<3;
    u64 acc[4][8];
#pragma unroll
    for(int i=0;i<4;i++)
#pragma unroll
        for(int j=0;j<8;j++) acc[i][j]=0ull;
    float4 bA=*(const float4*)(bias+n0), bB=*(const float4*)(bias+n0+4);
    stage_chunk(wbuf,Wg,tid); cp_commit();
    for(int c=0;c<8;c++){
        if(c<7){ stage_chunk(wbuf+((c+1)&1)*8192,Wg+(c+1)*8192,tid); cp_commit(); cp_wait1(); }
        else cp_wait0();
        __syncthreads();
        const float* wb=wbuf+(c&1)*8192;
#pragma unroll 8
        for(int kk=0;kk<32;kk++){
            int k=c*32+kk;
            const ulonglong2* hp=(const ulonglong2*)(actIn+SWZ(k,m0));
            ulonglong2 hA=hp[0],hB=hp[1];
            u64 h[4]={hA.x,hA.y,hB.x,hB.y};
            const float4* wr=(const float4*)(wb+kk*256+n0);
            float4 wa=wr[0],wv=wr[1];
            u64 w[8];
            w[0]=pack_dup(wa.x); w[1]=pack_dup(wa.y); w[2]=pack_dup(wa.z); w[3]=pack_dup(wa.w);
            w[4]=pack_dup(wv.x); w[5]=pack_dup(wv.y); w[6]=pack_dup(wv.z); w[7]=pack_dup(wv.w);
#pragma unroll
            for(int mi=0;mi<4;mi++)
#pragma unroll
                for(int nj=0;nj<8;nj++) acc[mi][nj]=ffma2(h[mi],w[nj],acc[mi][nj]);
        }
        __syncthreads();
    }
    float bn[8]={bA.x,bA.y,bA.z,bA.w,bB.x,bB.y,bB.z,bB.w};
#pragma unroll
    for(int nj=0;nj<8;nj++){
        int n=n0+nj; float o[8];
#pragma unroll
        for(int mi=0;mi<4;mi++){
            float2 v=unpack2(acc[mi][nj]);
            o[2*mi]=softplusf(v.x+bn[nj]); o[2*mi+1]=softplusf(v.y+bn[nj]);
        }
        float* dst=actOut+SWZ(n,m0);
        *(float4*)dst=make_float4(o[0],o[1],o[2],o[3]);
        *(float4*)(dst+4)=make_float4(o[4],o[5],o[6],o[7]);
    }
    __syncthreads();
}
__device__ __forceinline__ float layer4_val(const float* actIn,const float* __restrict__ W4,
        const float* __restrict__ b4,float* red,int tid){
    int m=tid&63,g=tid>>6; float s=0.f;
#pragma unroll 8
    for(int j=0;j<64;j++){ int k=g*64+j; s+=actIn[SWZ(k,m)]*W4[k]; }
    red[g*64+m]=s; __syncthreads();
    float v=0.f;
    if(tid<64) v=red[m]+red[64+m]+red[128+m]+red[192+m]+b4[0];
    return v;
}
__device__ __forceinline__ void eval_tile(float delta,float* actA,float* actB,float* wbuf,
    const float* __restrict__ W1,const float* __restrict__ b1,
    const float* __restrict__ W2,const float* __restrict__ b2,
    const float* __restrict__ W3,const float* __restrict__ b3,
    const float* __restrict__ W4,const float* __restrict__ b4,
    const float* s_o,const float* s_rd,const float* s_dp,float* s_f,int tid){
    int m=tid&63;
    float d=s_dp[m]+delta;
    float px=s_o[m]+d*s_rd[m], py=s_o[64+m]+d*s_rd[64+m], pz=s_o[128+m]+d*s_rd[128+m];
    int kbase=(tid>>6)*64;
#pragma unroll 8
    for(int j=0;j<64;j++){
        int k=kbase+j;
        float z=fmaf(px,W1[k],fmaf(py,W1[256+k],fmaf(pz,W1[512+k],b1[k])));
        actA[SWZ(k,m)]=softplusf(z);
    }
    gemm_layer(actA,W2,b2,actB,wbuf,tid);
    gemm_layer(actB,W3,b3,actA,wbuf,tid);
    float v=layer4_val(actA,W4,b4,wbuf,tid);
    if(tid<64) s_f[tid]=v;
    __syncthreads();
}
__global__ void __launch_bounds__(256,1)
k_refine(const float* __restrict__ ray0,const float* __restrict__ rdir,
         const float* __restrict__ W1,const float* __restrict__ b1,
         const float* __restrict__ W2,const float* __restrict__ b2,
         const float* __restrict__ W3,const float* __restrict__ b3,
         const float* __restrict__ W4,const float* __restrict__ b4,
         float* __restrict__ out){
    extern __shared__ float smf[];
    float* wbuf=smf; float* actA=smf+16384; float* actB=smf+32768;
    __shared__ float s_o[192],s_rd[192];
    __shared__ float s_dl[64],s_fl[64],s_dh[64],s_fh[64],s_dp[64],s_f[64],s_f0[64];
    __shared__ float s_a[64],s_b[64];
    __shared__ int s_mask[64];
    int tid=threadIdx.x, rbase=blockIdx.x*64;
    if(tid<64){
        int r=rbase+tid;
        s_o[tid]=ray0[3*r]; s_o[64+tid]=ray0[3*r+1]; s_o[128+tid]=ray0[3*r+2];
        s_rd[tid]=rdir[3*r]; s_rd[64+tid]=rdir[3*r+1]; s_rd[128+tid]=rdir[3*r+2];
        s_a[tid]=g_a[r]; s_b[tid]=g_b[r];
    }
    for(int i=tid;i<64*SSAMP;i+=256) wbuf[i]=g_val[rbase*SSAMP+i];
    __syncthreads();
    if(tid<64){
        const float* v=wbuf+tid*SSAMP;
        float best=1e30f; int bidx=0;
        for(int s=0;s<SSAMP;s++){
            float c;
            if(s<SSAMP-1){ float pr=v[s]*v[s+1];
                float sg=(pr>0.f)?1.f:((pr<0.f)?-1.f:0.f); c=sg*(float)(SSAMP-s); }
            else c=1.f;
            if(c<best){ best=c; bidx=s; }
        }
        float fl=v[bidx];
        int ihi=bidx+1; if(ihi>SSAMP-1) ihi=SSAMP-1;
        float dl=s_a[tid]+(float)bidx*s_b[tid];
        float dh=s_a[tid]+(float)ihi*s_b[tid];
        float fh=v[ihi];
        s_mask[tid]=(best<0.f)&&(fl<0.f)&&(v[0]<0.f);
        s_dl[tid]=dl; s_fl[tid]=fl; s_dh[tid]=dh; s_fh[tid]=fh;
        s_dp[tid]=secantf(dl,fl,dh,fh);
    }
    __syncthreads();
    for(int it=0;it<8;it++){
        eval_tile(0.f,actA,actB,wbuf,W1,b1,W2,b2,W3,b3,W4,b4,s_o,s_rd,s_dp,s_f,tid);
        if(tid<64){
            float fm=s_f[tid];
            float dl=s_dl[tid],fl=s_fl[tid],dh=s_dh[tid],fh=s_fh[tid],dp=s_dp[tid];
            if(fm<0.f){ dl=dp; fl=fm; } else { dh=dp; fh=fm; }
            s_dl[tid]=dl; s_fl[tid]=fl; s_dh[tid]=dh; s_fh[tid]=fh;
            s_dp[tid]=secantf(dl,fl,dh,fh);
        }
        __syncthreads();
    }
    eval_tile(0.f,actA,actB,wbuf,W1,b1,W2,b2,W3,b3,W4,b4,s_o,s_rd,s_dp,s_f,tid);
    if(tid<64) s_f0[tid]=s_f[tid];
    __syncthreads();
    eval_tile(-FDE,actA,actB,wbuf,W1,b1,W2,b2,W3,b3,W4,b4,s_o,s_rd,s_dp,s_f,tid);
    if(tid<64) s_fl[tid]=s_f[tid];
    __syncthreads();
    eval_tile(FDE,actA,actB,wbuf,W1,b1,W2,b2,W3,b3,W4,b4,s_o,s_rd,s_dp,s_f,tid);
    if(tid<64){
        float df=(s_f[tid]-s_fl[tid])*(0.5f/FDE);
        if(fabsf(df)<1e-6f) df=(df<0.f)?-1e-6f:1e-6f;
        float dout=s_dp[tid]-s_f0[tid]/df;
        out[rbase+tid]=s_mask[tid]?dout:0.f;
    }
}

extern "C" void kernel_launch(void* const* d_in,const int* in_sizes,int n_in,
                              void* d_out,int out_size){
    const float* ray0=(const float*)d_in[0];
    const float* rdir=(const float*)d_in[1];
    const float* W1=(const float*)d_in[2];
    const float* b1=(const float*)d_in[3];
    const float* W2=(const float*)d_in[4];
    const float* b2=(const float*)d_in[5];
    const float* W3=(const float*)d_in[6];
    const float* b3=(const float*)d_in[7];
    const float* W4=(const float*)d_in[8];
    const float* b4=(const float*)d_in[9];
    float* out=(float*)d_out;
    const int smemBig=98304;
    const int smemRef=49152*sizeof(float);
    cudaFuncSetAttribute(k_big,cudaFuncAttributeMaxDynamicSharedMemorySize,smemBig);
    cudaFuncSetAttribute(k_refine,cudaFuncAttributeMaxDynamicSharedMemorySize,smemRef);
    k_prep<<<512,256>>>(W2,W3);
    k_setup<<<(NRAYS+255)/256,256>>>(ray0,rdir);
    k_big<<<NRAYS*2,256,smemBig>>>(ray0,rdir,W1,b1,b2,b3,W4,b4);
    k_refine<<<NRAYS/64,256,smemRef>>>(ray0,rdir,W1,b1,W2,b2,W3,b3,W4,b4,out);
}

// round 8
// speedup vs baseline: 1.5179x; 1.5179x over previous
#include <cuda_runtime.h>
#include <cuda_bf16.h>
#include <cstdint>
typedef unsigned long long u64;
typedef unsigned int u32;

#define NRAYS 8192
#define SSAMP 128
#define P_DIST 0.55f
#define CUBE_EPS 1e-6f
#define FDE 2e-3f

__device__ float g_val[NRAYS * SSAMP];
__device__ float g_a[NRAYS];
__device__ float g_b[NRAYS];
// [layer][hi/lo]: 16 chunks x (256 n-rows x 48B pitch, 16 k bf16) = 196608 B
__device__ __align__(128) unsigned char g_WB[2][2][196608];

// ---- helpers ----
__device__ __forceinline__ u32 smem_u32(const void* p){ return (u32)__cvta_generic_to_shared(p); }
__device__ __forceinline__ float softplusf(float x){
    return fmaxf(x,0.f)+__logf(1.f+__expf(-fabsf(x)));
}
__device__ __forceinline__ float secantf(float dl,float fl,float dh,float fh){
    float den=fh-fl; if(fabsf(den)<1e-12f) den=1e-12f; return -fl*(dh-dl)/den+dl; }
__device__ __forceinline__ u64 pack_dup(float x){ u64 r; asm("mov.b64 %0,{%1,%2};":"=l"(r):"f"(x),"f"(x)); return r; }
__device__ __forceinline__ float2 unpack2(u64 v){ float2 f; asm("mov.b64 {%0,%1},%2;":"=f"(f.x),"=f"(f.y):"l"(v)); return f; }
__device__ __forceinline__ u64 ffma2(u64 a,u64 b,u64 c){ u64 d; asm("fma.rn.f32x2 %0,%1,%2,%3;":"=l"(d):"l"(a),"l"(b),"l"(c)); return d; }
__device__ __forceinline__ void cp16(u32 dst,const void* src){ asm volatile("cp.async.cg.shared.global [%0],[%1],16;"::"r"(dst),"l"(src):"memory"); }
__device__ __forceinline__ void cp_commit(){ asm volatile("cp.async.commit_group;":::"memory"); }
__device__ __forceinline__ void cp_wait0(){ asm volatile("cp.async.wait_group 0;":::"memory"); }
__device__ __forceinline__ void cp_wait1(){ asm volatile("cp.async.wait_group 1;":::"memory"); }

__device__ __forceinline__ void ldm4(u32* r,u32 a){
    asm volatile("ldmatrix.sync.aligned.m8n8.x4.shared.b16 {%0,%1,%2,%3},[%4];"
        :"=r"(r[0]),"=r"(r[1]),"=r"(r[2]),"=r"(r[3]):"r"(a)); }
__device__ __forceinline__ void mma16816(float* d,const u32* a,u32 b0,u32 b1){
    asm volatile("mma.sync.aligned.m16n8k16.row.col.f32.bf16.bf16.f32 "
        "{%0,%1,%2,%3},{%4,%5,%6,%7},{%8,%9},{%0,%1,%2,%3};"
        :"+f"(d[0]),"+f"(d[1]),"+f"(d[2]),"+f"(d[3])
        :"r"(a[0]),"r"(a[1]),"r"(a[2]),"r"(a[3]),"r"(b0),"r"(b1)); }
__device__ __forceinline__ void splitpk(float x,float y,u32&h,u32&l){
    __nv_bfloat16 hx=__float2bfloat16_rn(x), hy=__float2bfloat16_rn(y);
    __nv_bfloat16 lx=__float2bfloat16_rn(x-__bfloat162float(hx));
    __nv_bfloat16 ly=__float2bfloat16_rn(y-__bfloat162float(hy));
    h=((u32)*(unsigned short*)&hx)|(((u32)*(unsigned short*)&hy)<<16);
    l=((u32)*(unsigned short*)&lx)|(((u32)*(unsigned short*)&ly)<<16);
}

// ---- k_prep: W[k][n] fp32 -> [n][k]-major bf16 hi/lo chunk blobs ----
__global__ void k_prep(const float* __restrict__ W2,const float* __restrict__ W3){
    int idx=blockIdx.x*blockDim.x+threadIdx.x;
    int layer=idx>>16, e=idx&65535;
    const float* W=layer?W3:W2;
    int k=e>>8, n=e&255;
    float w=W[e];
    __nv_bfloat16 hi=__float2bfloat16_rn(w);
    __nv_bfloat16 lo=__float2bfloat16_rn(w-__bfloat162float(hi));
    int c=k>>4, kk=k&15;
    size_t off=(size_t)c*12288+(size_t)n*48+(size_t)kk*2;
    *(__nv_bfloat16*)(g_WB[layer][0]+off)=hi;
    *(__nv_bfloat16*)(g_WB[layer][1]+off)=lo;
}

// ---- cube intersection ----
__global__ void k_setup(const float* __restrict__ ray0,const float* __restrict__ rdir){
    int r=blockIdx.x*blockDim.x+threadIdx.x; if(r>=NRAYS) return;
    float o0=ray0[3*r],o1=ray0[3*r+1],o2=ray0[3*r+2];
    float r0=rdir[3*r],r1=rdir[3*r+1],r2=rdir[3*r+2];
    float ov[3]={o0,o1,o2},rv[3]={r0,r1,r2},t2[2]={0.f,0.f};
    int cnt=0; float rn=sqrtf(r0*r0+r1*r1+r2*r2);
#pragma unroll
    for(int i=0;i<6;i++){
        int ax=i%3; float pv=(i<3)?P_DIST:-P_DIST;
        float den=rv[ax]; if(fabsf(den)<1e-9f) den=1e-9f;
        float t=(pv-ov[ax])/den;
        float q0=o0+t*r0,q1=o1+t*r1,q2=o2+t*r2;
        bool ins=(fabsf(q0)<=P_DIST+CUBE_EPS)&&(fabsf(q1)<=P_DIST+CUBE_EPS)&&(fabsf(q2)<=P_DIST+CUBE_EPS);
        if(ins){ if(cnt<2){ float e0=q0-o0,e1=q1-o1,e2=q2-o2;
                t2[cnt]=sqrtf(e0*e0+e1*e1+e2*e2)/rn; } cnt++; }
    }
    float a,b;
    if(cnt==2){ float lo=fminf(t2[0],t2[1]),hi=fmaxf(t2[0],t2[1]); a=lo; b=(hi-lo)*(1.f/127.f); }
    else { a=0.f; b=2.4f/127.f; }
    g_a[r]=a; g_b[r]=b;
}

// ---- k_big: one ray/CTA, 8 warps 2m x 4n, split-3 bf16 mma (R6 config) ----
#define ABH 0
#define ABL 65536
#define BBF 131072
__device__ __forceinline__ void stageB(char* dst,const unsigned char* sH,const unsigned char* sL,int tid){
    u32 d=smem_u32(dst);
#pragma unroll
    for(int j=0;j<3;j++){ int u=tid+j*256; cp16(d+u*16,sH+u*16); }
#pragma unroll
    for(int j=0;j<3;j++){ int u=tid+j*256; cp16(d+12288+u*16,sL+u*16); }
}

__global__ void __launch_bounds__(256,1)
k_big(const float* __restrict__ ray0,const float* __restrict__ rdir,
      const float* __restrict__ W1,const float* __restrict__ b1,
      const float* __restrict__ b2,const float* __restrict__ b3,
      const float* __restrict__ W4,const float* __restrict__ b4){
    extern __shared__ char sm[];
    __shared__ float s_bias[256], s_w4[256], s_red[512], s_c[512];
    int tid=threadIdx.x, lane=tid&31, warp=tid>>5, ray=blockIdx.x;
    u32 smb=smem_u32(sm);

    float a=g_a[ray], st=g_b[ray];
    float ox=ray0[ray*3],oy=ray0[ray*3+1],oz=ray0[ray*3+2];
    float dx=rdir[ray*3],dy=rdir[ray*3+1],dz=rdir[ray*3+2];
    // per-k affine coefficients: z(d,k)=c0[k]+d*c1[k]
    s_c[2*tid]  =fmaf(ox,W1[tid],fmaf(oy,W1[256+tid],fmaf(oz,W1[512+tid],b1[tid])));
    s_c[2*tid+1]=fmaf(dx,W1[tid],fmaf(dy,W1[256+tid],dz*W1[512+tid]));
    __syncthreads();
    {
        int m=tid&127, kh=tid>>7;
        float d=a+(float)m*st;
#pragma unroll 4
        for(int j=0;j<128;j+=2){
            int k=kh*128+j;
            float2 ca=*(float2*)(s_c+2*k);
            float2 cb=*(float2*)(s_c+2*k+2);
            float v0=softplusf(fmaf(d,ca.y,ca.x));
            float v1=softplusf(fmaf(d,cb.y,cb.x));
            u32 h,l; splitpk(v0,v1,h,l);
            int off=m*512+((((k>>3))^(m&7))<<4)+((k&7)<<1);
            *(u32*)(sm+ABH+off)=h;
            *(u32*)(sm+ABL+off)=l;
        }
    }

    int g2=lane>>3, row=lane&7;
    int mw=warp&1, nw=warp>>1;
    int m0=mw*64, n0=nw*64;
    u32 arow=(u32)((m0+(g2&1)*8+row)*512);
    u32 boff=(u32)((n0+(g2>>1)*8+row)*48+(g2&1)*16);

    for(int L=0;L<2;L++){
        s_bias[tid]=L?b3[tid]:b2[tid];
        if(L) s_w4[tid]=W4[tid];
        const unsigned char* blobH=g_WB[L][0];
        const unsigned char* blobL=g_WB[L][1];
        float acc[4][8][4];
#pragma unroll
        for(int i=0;i<4;i++)
#pragma unroll
            for(int j=0;j<8;j++){ acc[i][j][0]=0.f; acc[i][j][1]=0.f; acc[i][j][2]=0.f; acc[i][j][3]=0.f; }
        stageB(sm+BBF,blobH,blobL,tid); cp_commit();
        for(int c=0;c<16;c++){
            cp_wait0();
            __syncthreads();
            if(c<15){ stageB(sm+BBF+((c+1)&1)*24576,blobH+(c+1)*12288,blobL+(c+1)*12288,tid); cp_commit(); }
            u32 bb=smb+BBF+(c&1)*24576;
            u32 bh[4][4], bl[4][4];
#pragma unroll
            for(int j=0;j<4;j++){
                u32 ba=bb+boff+j*768;
                ldm4(bh[j],ba);
                ldm4(bl[j],ba+12288);
            }
            u32 au=(u32)(((2*c+(g2>>1))^row)<<4);
            u32 ah[2][4], al[2][4];
            ldm4(ah[0],smb+ABH+arow+au);
            ldm4(al[0],smb+ABL+arow+au);
#pragma unroll
            for(int mt=0;mt<4;mt++){
                int cur=mt&1;
                if(mt<3){
                    ldm4(ah[cur^1],smb+ABH+arow+(u32)((mt+1)*8192)+au);
                    ldm4(al[cur^1],smb+ABL+arow+(u32)((mt+1)*8192)+au);
                }
#pragma unroll
                for(int p=0;p<3;p++){
                    const u32* A=(p==2)?al[cur]:ah[cur];
#pragma unroll
                    for(int nt=0;nt<8;nt++){
                        const u32* B=(p==1)?bl[nt>>1]:bh[nt>>1];
                        mma16816(acc[mt][nt],A,B[(nt&1)*2],B[(nt&1)*2+1]);
                    }
                }
            }
        }
        __syncthreads();
        if(L==0){
#pragma unroll
            for(int mt=0;mt<4;mt++){
                int r0=m0+mt*16+(lane>>2), r1=r0+8;
#pragma unroll
                for(int nt=0;nt<8;nt++){
                    int n=n0+nt*8+(lane&3)*2;
                    float v0=softplusf(acc[mt][nt][0]+s_bias[n]);
                    float v1=softplusf(acc[mt][nt][1]+s_bias[n+1]);
                    float v2=softplusf(acc[mt][nt][2]+s_bias[n]);
                    float v3=softplusf(acc[mt][nt][3]+s_bias[n+1]);
                    u32 h0,l0,h1,l1;
                    splitpk(v0,v1,h0,l0);
                    splitpk(v2,v3,h1,l1);
                    int o0=r0*512+(((n>>3)^(r0&7))<<4)+(n&7)*2;
                    int o1=r1*512+(((n>>3)^(r1&7))<<4)+(n&7)*2;
                    *(u32*)(sm+ABH+o0)=h0; *(u32*)(sm+ABL+o0)=l0;
                    *(u32*)(sm+ABH+o1)=h1; *(u32*)(sm+ABL+o1)=l1;
                }
            }
        } else {
#pragma unroll
            for(int mt=0;mt<4;mt++){
                float s0=0.f,s1=0.f;
#pragma unroll
                for(int nt=0;nt<8;nt++){
                    int n=n0+nt*8+(lane&3)*2;
                    s0+=softplusf(acc[mt][nt][0]+s_bias[n])*s_w4[n]
                       +softplusf(acc[mt][nt][1]+s_bias[n+1])*s_w4[n+1];
                    s1+=softplusf(acc[mt][nt][2]+s_bias[n])*s_w4[n]
                       +softplusf(acc[mt][nt][3]+s_bias[n+1])*s_w4[n+1];
                }
                s0+=__shfl_xor_sync(0xffffffffu,s0,1); s0+=__shfl_xor_sync(0xffffffffu,s0,2);
                s1+=__shfl_xor_sync(0xffffffffu,s1,1); s1+=__shfl_xor_sync(0xffffffffu,s1,2);
                if((lane&3)==0){
                    int r0=m0+mt*16+(lane>>2);
                    s_red[r0*4+nw]=s0;
                    s_red[(r0+8)*4+nw]=s1;
                }
            }
            __syncthreads();
            if(tid<128)
                g_val[ray*SSAMP+tid]=s_red[tid*4]+s_red[tid*4+1]+s_red[tid*4+2]+s_red[tid*4+3]+b4[0];
        }
        __syncthreads();
    }
}

// ======== exact-fp32 FFMA refinement, 512 threads ========
__device__ __forceinline__ int SWZ(int k,int m){ return (k<<6)+(m^(((k>>3)&7)<<3)); }
__device__ __forceinline__ void stage_chunk(float* wdst,const float* __restrict__ Wsrc,int tid){
    u32 d=smem_u32(wdst)+(u32)tid*16u; const float* s=Wsrc+tid*4;
#pragma unroll
    for(int j=0;j<4;j++) cp16(d+(u32)j*8192u,s+j*2048);
}
__device__ __forceinline__ void gemm_layer(const float* actIn,const float* __restrict__ Wg,
        const float* __restrict__ bias,float* actOut,float* wbuf,int tid){
    const int m0=(tid>>5)<<2;      // warp*4
    const int n0=(tid&31)<<3;      // lane*8
    u64 acc[2][8];
#pragma unroll
    for(int i=0;i<2;i++)
#pragma unroll
        for(int j=0;j<8;j++) acc[i][j]=0ull;
    float4 bA=*(const float4*)(bias+n0), bB=*(const float4*)(bias+n0+4);
    stage_chunk(wbuf,Wg,tid); cp_commit();
    for(int c=0;c<8;c++){
        if(c<7){ stage_chunk(wbuf+((c+1)&1)*8192,Wg+(c+1)*8192,tid); cp_commit(); cp_wait1(); }
        else cp_wait0();
        __syncthreads();
        const float* wb=wbuf+(c&1)*8192;
#pragma unroll 8
        for(int kk=0;kk<32;kk++){
            int k=c*32+kk;
            const ulonglong2* hp=(const ulonglong2*)(actIn+SWZ(k,m0));
            ulonglong2 hA=hp[0];
            u64 h[2]={hA.x,hA.y};
            const float4* wr=(const float4*)(wb+kk*256+n0);
            float4 wa=wr[0],wv=wr[1];
            u64 w[8];
            w[0]=pack_dup(wa.x); w[1]=pack_dup(wa.y); w[2]=pack_dup(wa.z); w[3]=pack_dup(wa.w);
            w[4]=pack_dup(wv.x); w[5]=pack_dup(wv.y); w[6]=pack_dup(wv.z); w[7]=pack_dup(wv.w);
#pragma unroll
            for(int mi=0;mi<2;mi++)
#pragma unroll
                for(int nj=0;nj<8;nj++) acc[mi][nj]=ffma2(h[mi],w[nj],acc[mi][nj]);
        }
        __syncthreads();
    }
    float bn[8]={bA.x,bA.y,bA.z,bA.w,bB.x,bB.y,bB.z,bB.w};
#pragma unroll
    for(int nj=0;nj<8;nj++){
        int n=n0+nj; float o[4];
#pragma unroll
        for(int mi=0;mi<2;mi++){
            float2 v=unpack2(acc[mi][nj]);
            o[2*mi]=softplusf(v.x+bn[nj]); o[2*mi+1]=softplusf(v.y+bn[nj]);
        }
        float* dst=actOut+SWZ(n,m0);
        *(float4*)dst=make_float4(o[0],o[1],o[2],o[3]);
    }
    __syncthreads();
}
__device__ __forceinline__ float layer4_val(const float* actIn,const float* __restrict__ W4,
        const float* __restrict__ b4,float* red,int tid){
    int m=tid&63,g=tid>>6; float s=0.f;   // 8 groups of 32 k
#pragma unroll 8
    for(int j=0;j<32;j++){ int k=g*32+j; s+=actIn[SWZ(k,m)]*W4[k]; }
    red[g*64+m]=s; __syncthreads();
    float v=0.f;
    if(tid<64){
        v=b4[0];
#pragma unroll
        for(int g2=0;g2<8;g2++) v+=red[g2*64+m];
    }
    return v;
}
__device__ __forceinline__ void eval_tile(float delta,float* actA,float* actB,float* wbuf,
    const float* __restrict__ W1,const float* __restrict__ b1,
    const float* __restrict__ W2,const float* __restrict__ b2,
    const float* __restrict__ W3,const float* __restrict__ b3,
    const float* __restrict__ W4,const float* __restrict__ b4,
    const float* s_o,const float* s_rd,const float* s_dp,float* s_f,int tid){
    int m=tid&63;
    float d=s_dp[m]+delta;
    float px=s_o[m]+d*s_rd[m], py=s_o[64+m]+d*s_rd[64+m], pz=s_o[128+m]+d*s_rd[128+m];
    int kbase=(tid>>6)*32;   // 8 groups of 32 k
#pragma unroll 8
    for(int j=0;j<32;j++){
        int k=kbase+j;
        float z=fmaf(px,W1[k],fmaf(py,W1[256+k],fmaf(pz,W1[512+k],b1[k])));
        actA[SWZ(k,m)]=softplusf(z);
    }
    gemm_layer(actA,W2,b2,actB,wbuf,tid);
    gemm_layer(actB,W3,b3,actA,wbuf,tid);
    float v=layer4_val(actA,W4,b4,wbuf,tid);
    if(tid<64) s_f[tid]=v;
    __syncthreads();
}
__global__ void __launch_bounds__(512,1)
k_refine(const float* __restrict__ ray0,const float* __restrict__ rdir,
         const float* __restrict__ W1,const float* __restrict__ b1,
         const float* __restrict__ W2,const float* __restrict__ b2,
         const float* __restrict__ W3,const float* __restrict__ b3,
         const float* __restrict__ W4,const float* __restrict__ b4,
         float* __restrict__ out){
    extern __shared__ float smf[];
    float* wbuf=smf; float* actA=smf+16384; float* actB=smf+32768;
    __shared__ float s_o[192],s_rd[192];
    __shared__ float s_dl[64],s_fl[64],s_dh[64],s_fh[64],s_dp[64],s_f[64],s_f0[64];
    __shared__ float s_a[64],s_b[64];
    __shared__ int s_mask[64];
    int tid=threadIdx.x, rbase=blockIdx.x*64;
    if(tid<64){
        int r=rbase+tid;
        s_o[tid]=ray0[3*r]; s_o[64+tid]=ray0[3*r+1]; s_o[128+tid]=ray0[3*r+2];
        s_rd[tid]=rdir[3*r]; s_rd[64+tid]=rdir[3*r+1]; s_rd[128+tid]=rdir[3*r+2];
        s_a[tid]=g_a[r]; s_b[tid]=g_b[r];
    }
    for(int i=tid;i<64*SSAMP;i+=512) wbuf[i]=g_val[rbase*SSAMP+i];
    __syncthreads();
    if(tid<64){
        const float* v=wbuf+tid*SSAMP;
        float best=1e30f; int bidx=0;
        for(int s=0;s<SSAMP;s++){
            float c;
            if(s<SSAMP-1){ float pr=v[s]*v[s+1];
                float sg=(pr>0.f)?1.f:((pr<0.f)?-1.f:0.f); c=sg*(float)(SSAMP-s); }
            else c=1.f;
            if(c<best){ best=c; bidx=s; }
        }
        float fl=v[bidx];
        int ihi=bidx+1; if(ihi>SSAMP-1) ihi=SSAMP-1;
        float dl=s_a[tid]+(float)bidx*s_b[tid];
        float dh=s_a[tid]+(float)ihi*s_b[tid];
        float fh=v[ihi];
        s_mask[tid]=(best<0.f)&&(fl<0.f)&&(v[0]<0.f);
        s_dl[tid]=dl; s_fl[tid]=fl; s_dh[tid]=dh; s_fh[tid]=fh;
        s_dp[tid]=secantf(dl,fl,dh,fh);
    }
    __syncthreads();
    for(int it=0;it<8;it++){
        eval_tile(0.f,actA,actB,wbuf,W1,b1,W2,b2,W3,b3,W4,b4,s_o,s_rd,s_dp,s_f,tid);
        if(tid<64){
            float fm=s_f[tid];
            float dl=s_dl[tid],fl=s_fl[tid],dh=s_dh[tid],fh=s_fh[tid],dp=s_dp[tid];
            if(fm<0.f){ dl=dp; fl=fm; } else { dh=dp; fh=fm; }
            s_dl[tid]=dl; s_fl[tid]=fl; s_dh[tid]=dh; s_fh[tid]=fh;
            s_dp[tid]=secantf(dl,fl,dh,fh);
        }
        __syncthreads();
    }
    eval_tile(0.f,actA,actB,wbuf,W1,b1,W2,b2,W3,b3,W4,b4,s_o,s_rd,s_dp,s_f,tid);
    if(tid<64) s_f0[tid]=s_f[tid];
    __syncthreads();
    eval_tile(-FDE,actA,actB,wbuf,W1,b1,W2,b2,W3,b3,W4,b4,s_o,s_rd,s_dp,s_f,tid);
    if(tid<64) s_fl[tid]=s_f[tid];
    __syncthreads();
    eval_tile(FDE,actA,actB,wbuf,W1,b1,W2,b2,W3,b3,W4,b4,s_o,s_rd,s_dp,s_f,tid);
    if(tid<64){
        float df=(s_f[tid]-s_fl[tid])*(0.5f/FDE);
        if(fabsf(df)<1e-6f) df=(df<0.f)?-1e-6f:1e-6f;
        float dout=s_dp[tid]-s_f0[tid]/df;
        out[rbase+tid]=s_mask[tid]?dout:0.f;
    }
}

extern "C" void kernel_launch(void* const* d_in,const int* in_sizes,int n_in,
                              void* d_out,int out_size){
    const float* ray0=(const float*)d_in[0];
    const float* rdir=(const float*)d_in[1];
    const float* W1=(const float*)d_in[2];
    const float* b1=(const float*)d_in[3];
    const float* W2=(const float*)d_in[4];
    const float* b2=(const float*)d_in[5];
    const float* W3=(const float*)d_in[6];
    const float* b3=(const float*)d_in[7];
    const float* W4=(const float*)d_in[8];
    const float* b4=(const float*)d_in[9];
    float* out=(float*)d_out;
    const int smemBig=180224;
    const int smemRef=49152*sizeof(float);
    cudaFuncSetAttribute(k_big,cudaFuncAttributeMaxDynamicSharedMemorySize,smemBig);
    cudaFuncSetAttribute(k_refine,cudaFuncAttributeMaxDynamicSharedMemorySize,smemRef);
    k_prep<<<512,256>>>(W2,W3);
    k_setup<<<(NRAYS+255)/256,256>>>(ray0,rdir);
    k_big<<<NRAYS,256,smemBig>>>(ray0,rdir,W1,b1,b2,b3,W4,b4);
    k_refine<<<NRAYS/64,512,smemRef>>>(ray0,rdir,W1,b1,W2,b2,W3,b3,W4,b4,out);
}

// round 9
// speedup vs baseline: 1.8268x; 1.2035x over previous
#include <cuda_runtime.h>
#include <cuda_bf16.h>
#include <cstdint>
typedef unsigned long long u64;
typedef unsigned int u32;

#define NRAYS 8192
#define SSAMP 128
#define P_DIST 0.55f
#define CUBE_EPS 1e-6f
#define FDE 2e-3f

__device__ float g_val[NRAYS * SSAMP];
__device__ float g_a[NRAYS];
__device__ float g_b[NRAYS];
// [layer][hi/lo]: 16 chunks x (256 n-rows x 48B pitch, 16 k bf16) = 196608 B
__device__ __align__(128) unsigned char g_WB[2][2][196608];

// ---- helpers ----
__device__ __forceinline__ u32 smem_u32(const void* p){ return (u32)__cvta_generic_to_shared(p); }
__device__ __forceinline__ float softplusf(float x){
    return fmaxf(x,0.f)+__logf(1.f+__expf(-fabsf(x)));
}
__device__ __forceinline__ float secantf(float dl,float fl,float dh,float fh){
    float den=fh-fl; if(fabsf(den)<1e-12f) den=1e-12f; return -fl*(dh-dl)/den+dl; }
__device__ __forceinline__ void cp16(u32 dst,const void* src){ asm volatile("cp.async.cg.shared.global [%0],[%1],16;"::"r"(dst),"l"(src):"memory"); }
__device__ __forceinline__ void cp_commit(){ asm volatile("cp.async.commit_group;":::"memory"); }
__device__ __forceinline__ void cp_wait0(){ asm volatile("cp.async.wait_group 0;":::"memory"); }

__device__ __forceinline__ void ldm4(u32* r,u32 a){
    asm volatile("ldmatrix.sync.aligned.m8n8.x4.shared.b16 {%0,%1,%2,%3},[%4];"
        :"=r"(r[0]),"=r"(r[1]),"=r"(r[2]),"=r"(r[3]):"r"(a)); }
__device__ __forceinline__ void mma16816(float* d,const u32* a,u32 b0,u32 b1){
    asm volatile("mma.sync.aligned.m16n8k16.row.col.f32.bf16.bf16.f32 "
        "{%0,%1,%2,%3},{%4,%5,%6,%7},{%8,%9},{%0,%1,%2,%3};"
        :"+f"(d[0]),"+f"(d[1]),"+f"(d[2]),"+f"(d[3])
        :"r"(a[0]),"r"(a[1]),"r"(a[2]),"r"(a[3]),"r"(b0),"r"(b1)); }
__device__ __forceinline__ void splitpk(float x,float y,u32&h,u32&l){
    __nv_bfloat16 hx=__float2bfloat16_rn(x), hy=__float2bfloat16_rn(y);
    __nv_bfloat16 lx=__float2bfloat16_rn(x-__bfloat162float(hx));
    __nv_bfloat16 ly=__float2bfloat16_rn(y-__bfloat162float(hy));
    h=((u32)*(unsigned short*)&hx)|(((u32)*(unsigned short*)&hy)<<16);
    l=((u32)*(unsigned short*)&lx)|(((u32)*(unsigned short*)&ly)<<16);
}

// ---- k_prep ----
__global__ void k_prep(const float* __restrict__ W2,const float* __restrict__ W3){
    int idx=blockIdx.x*blockDim.x+threadIdx.x;
    int layer=idx>>16, e=idx&65535;
    const float* W=layer?W3:W2;
    int k=e>>8, n=e&255;
    float w=W[e];
    __nv_bfloat16 hi=__float2bfloat16_rn(w);
    __nv_bfloat16 lo=__float2bfloat16_rn(w-__bfloat162float(hi));
    int c=k>>4, kk=k&15;
    size_t off=(size_t)c*12288+(size_t)n*48+(size_t)kk*2;
    *(__nv_bfloat16*)(g_WB[layer][0]+off)=hi;
    *(__nv_bfloat16*)(g_WB[layer][1]+off)=lo;
}

// ---- cube intersection ----
__global__ void k_setup(const float* __restrict__ ray0,const float* __restrict__ rdir){
    int r=blockIdx.x*blockDim.x+threadIdx.x; if(r>=NRAYS) return;
    float o0=ray0[3*r],o1=ray0[3*r+1],o2=ray0[3*r+2];
    float r0=rdir[3*r],r1=rdir[3*r+1],r2=rdir[3*r+2];
    float ov[3]={o0,o1,o2},rv[3]={r0,r1,r2},t2[2]={0.f,0.f};
    int cnt=0; float rn=sqrtf(r0*r0+r1*r1+r2*r2);
#pragma unroll
    for(int i=0;i<6;i++){
        int ax=i%3; float pv=(i<3)?P_DIST:-P_DIST;
        float den=rv[ax]; if(fabsf(den)<1e-9f) den=1e-9f;
        float t=(pv-ov[ax])/den;
        float q0=o0+t*r0,q1=o1+t*r1,q2=o2+t*r2;
        bool ins=(fabsf(q0)<=P_DIST+CUBE_EPS)&&(fabsf(q1)<=P_DIST+CUBE_EPS)&&(fabsf(q2)<=P_DIST+CUBE_EPS);
        if(ins){ if(cnt<2){ float e0=q0-o0,e1=q1-o1,e2=q2-o2;
                t2[cnt]=sqrtf(e0*e0+e1*e1+e2*e2)/rn; } cnt++; }
    }
    float a,b;
    if(cnt==2){ float lo=fminf(t2[0],t2[1]),hi=fmaxf(t2[0],t2[1]); a=lo; b=(hi-lo)*(1.f/127.f); }
    else { a=0.f; b=2.4f/127.f; }
    g_a[r]=a; g_b[r]=b;
}

// ---- stageB: 24KB weight chunk (hi 12288 + lo 12288) ----
__device__ __forceinline__ void stageB(char* dst,const unsigned char* sH,const unsigned char* sL,int tid){
    u32 d=smem_u32(dst);
#pragma unroll
    for(int j=0;j<3;j++){ int u=tid+j*256; cp16(d+u*16,sH+u*16); }
#pragma unroll
    for(int j=0;j<3;j++){ int u=tid+j*256; cp16(d+12288+u*16,sL+u*16); }
}

// ---- k_big: one ray/CTA, 8 warps 2m x 4n, split-3 bf16 mma (R8 config) ----
#define ABH 0
#define ABL 65536
#define BBF 131072
__global__ void __launch_bounds__(256,1)
k_big(const float* __restrict__ ray0,const float* __restrict__ rdir,
      const float* __restrict__ W1,const float* __restrict__ b1,
      const float* __restrict__ b2,const float* __restrict__ b3,
      const float* __restrict__ W4,const float* __restrict__ b4){
    extern __shared__ char sm[];
    __shared__ float s_bias[256], s_w4[256], s_red[512], s_c[512];
    int tid=threadIdx.x, lane=tid&31, warp=tid>>5, ray=blockIdx.x;
    u32 smb=smem_u32(sm);

    float a=g_a[ray], st=g_b[ray];
    float ox=ray0[ray*3],oy=ray0[ray*3+1],oz=ray0[ray*3+2];
    float dx=rdir[ray*3],dy=rdir[ray*3+1],dz=rdir[ray*3+2];
    s_c[2*tid]  =fmaf(ox,W1[tid],fmaf(oy,W1[256+tid],fmaf(oz,W1[512+tid],b1[tid])));
    s_c[2*tid+1]=fmaf(dx,W1[tid],fmaf(dy,W1[256+tid],dz*W1[512+tid]));
    __syncthreads();
    {
        int m=tid&127, kh=tid>>7;
        float d=a+(float)m*st;
#pragma unroll 4
        for(int j=0;j<128;j+=2){
            int k=kh*128+j;
            float2 ca=*(float2*)(s_c+2*k);
            float2 cb=*(float2*)(s_c+2*k+2);
            float v0=softplusf(fmaf(d,ca.y,ca.x));
            float v1=softplusf(fmaf(d,cb.y,cb.x));
            u32 h,l; splitpk(v0,v1,h,l);
            int off=m*512+((((k>>3))^(m&7))<<4)+((k&7)<<1);
            *(u32*)(sm+ABH+off)=h;
            *(u32*)(sm+ABL+off)=l;
        }
    }

    int g2=lane>>3, row=lane&7;
    int mw=warp&1, nw=warp>>1;
    int m0=mw*64, n0=nw*64;
    u32 arow=(u32)((m0+(g2&1)*8+row)*512);
    u32 boff=(u32)((n0+(g2>>1)*8+row)*48+(g2&1)*16);

    for(int L=0;L<2;L++){
        s_bias[tid]=L?b3[tid]:b2[tid];
        if(L) s_w4[tid]=W4[tid];
        const unsigned char* blobH=g_WB[L][0];
        const unsigned char* blobL=g_WB[L][1];
        float acc[4][8][4];
#pragma unroll
        for(int i=0;i<4;i++)
#pragma unroll
            for(int j=0;j<8;j++){ acc[i][j][0]=0.f; acc[i][j][1]=0.f; acc[i][j][2]=0.f; acc[i][j][3]=0.f; }
        stageB(sm+BBF,blobH,blobL,tid); cp_commit();
        for(int c=0;c<16;c++){
            cp_wait0();
            __syncthreads();
            if(c<15){ stageB(sm+BBF+((c+1)&1)*24576,blobH+(c+1)*12288,blobL+(c+1)*12288,tid); cp_commit(); }
            u32 bb=smb+BBF+(c&1)*24576;
            u32 bh[4][4], bl[4][4];
#pragma unroll
            for(int j=0;j<4;j++){
                u32 ba=bb+boff+j*768;
                ldm4(bh[j],ba);
                ldm4(bl[j],ba+12288);
            }
            u32 au=(u32)(((2*c+(g2>>1))^row)<<4);
            u32 ah[2][4], al[2][4];
            ldm4(ah[0],smb+ABH+arow+au);
            ldm4(al[0],smb+ABL+arow+au);
#pragma unroll
            for(int mt=0;mt<4;mt++){
                int cur=mt&1;
                if(mt<3){
                    ldm4(ah[cur^1],smb+ABH+arow+(u32)((mt+1)*8192)+au);
                    ldm4(al[cur^1],smb+ABL+arow+(u32)((mt+1)*8192)+au);
                }
#pragma unroll
                for(int p=0;p<3;p++){
                    const u32* A=(p==2)?al[cur]:ah[cur];
#pragma unroll
                    for(int nt=0;nt<8;nt++){
                        const u32* B=(p==1)?bl[nt>>1]:bh[nt>>1];
                        mma16816(acc[mt][nt],A,B[(nt&1)*2],B[(nt&1)*2+1]);
                    }
                }
            }
        }
        __syncthreads();
        if(L==0){
#pragma unroll
            for(int mt=0;mt<4;mt++){
                int r0=m0+mt*16+(lane>>2), r1=r0+8;
#pragma unroll
                for(int nt=0;nt<8;nt++){
                    int n=n0+nt*8+(lane&3)*2;
                    float v0=softplusf(acc[mt][nt][0]+s_bias[n]);
                    float v1=softplusf(acc[mt][nt][1]+s_bias[n+1]);
                    float v2=softplusf(acc[mt][nt][2]+s_bias[n]);
                    float v3=softplusf(acc[mt][nt][3]+s_bias[n+1]);
                    u32 h0,l0,h1,l1;
                    splitpk(v0,v1,h0,l0);
                    splitpk(v2,v3,h1,l1);
                    int o0=r0*512+(((n>>3)^(r0&7))<<4)+(n&7)*2;
                    int o1=r1*512+(((n>>3)^(r1&7))<<4)+(n&7)*2;
                    *(u32*)(sm+ABH+o0)=h0; *(u32*)(sm+ABL+o0)=l0;
                    *(u32*)(sm+ABH+o1)=h1; *(u32*)(sm+ABL+o1)=l1;
                }
            }
        } else {
#pragma unroll
            for(int mt=0;mt<4;mt++){
                float s0=0.f,s1=0.f;
#pragma unroll
                for(int nt=0;nt<8;nt++){
                    int n=n0+nt*8+(lane&3)*2;
                    s0+=softplusf(acc[mt][nt][0]+s_bias[n])*s_w4[n]
                       +softplusf(acc[mt][nt][1]+s_bias[n+1])*s_w4[n+1];
                    s1+=softplusf(acc[mt][nt][2]+s_bias[n])*s_w4[n]
                       +softplusf(acc[mt][nt][3]+s_bias[n+1])*s_w4[n+1];
                }
                s0+=__shfl_xor_sync(0xffffffffu,s0,1); s0+=__shfl_xor_sync(0xffffffffu,s0,2);
                s1+=__shfl_xor_sync(0xffffffffu,s1,1); s1+=__shfl_xor_sync(0xffffffffu,s1,2);
                if((lane&3)==0){
                    int r0=m0+mt*16+(lane>>2);
                    s_red[r0*4+nw]=s0;
                    s_red[(r0+8)*4+nw]=s1;
                }
            }
            __syncthreads();
            if(tid<128)
                g_val[ray*SSAMP+tid]=s_red[tid*4]+s_red[tid*4+1]+s_red[tid*4+2]+s_red[tid*4+3]+b4[0];
        }
        __syncthreads();
    }
}

// ======== k_refine: HMMA split-3 evals, M=64 (64 rays/CTA) ========
#define RBH 0
#define RBL 32768
#define RBB 65536   // 2 x 24576
__device__ __forceinline__ void eval_mma(char* sm,u32 smb,int tid,float delta,
    const float* __restrict__ W1,const float* __restrict__ b1,
    const float* s_o,const float* s_rd,const float* s_dp,
    const float* s_bias2,const float* s_bias3,const float* s_w4,float b4v,
    float* s_red,float* s_f){
    int lane=tid&31, warp=tid>>5;
    // layer 1 -> A planes (64 m x 256 k)
    {
        int m=tid&63, kg=tid>>6;
        float d=s_dp[m]+delta;
        float px=s_o[m]+d*s_rd[m], py=s_o[64+m]+d*s_rd[64+m], pz=s_o[128+m]+d*s_rd[128+m];
#pragma unroll 4
        for(int j=0;j<64;j+=2){
            int k=kg*64+j;
            float z0=fmaf(px,W1[k],fmaf(py,W1[256+k],fmaf(pz,W1[512+k],b1[k])));
            float z1=fmaf(px,W1[k+1],fmaf(py,W1[257+k],fmaf(pz,W1[513+k],b1[k+1])));
            float v0=softplusf(z0), v1=softplusf(z1);
            u32 h,l; splitpk(v0,v1,h,l);
            int off=m*512+((((k>>3))^(m&7))<<4)+((k&7)<<1);
            *(u32*)(sm+RBH+off)=h;
            *(u32*)(sm+RBL+off)=l;
        }
    }
    int g2=lane>>3, row=lane&7;
    int mw=warp&1, nw=warp>>1;
    int m0=mw*32, n0=nw*64;
    u32 arow=(u32)((m0+(g2&1)*8+row)*512);
    u32 boff=(u32)((n0+(g2>>1)*8+row)*48+(g2&1)*16);

    for(int L=0;L<2;L++){
        const float* bias=L?s_bias3:s_bias2;
        const unsigned char* blobH=g_WB[L][0];
        const unsigned char* blobL=g_WB[L][1];
        float acc[2][8][4];
#pragma unroll
        for(int i=0;i<2;i++)
#pragma unroll
            for(int j=0;j<8;j++){ acc[i][j][0]=0.f; acc[i][j][1]=0.f; acc[i][j][2]=0.f; acc[i][j][3]=0.f; }
        stageB(sm+RBB,blobH,blobL,tid); cp_commit();
        for(int c=0;c<16;c++){
            cp_wait0();
            __syncthreads();
            if(c<15){ stageB(sm+RBB+((c+1)&1)*24576,blobH+(c+1)*12288,blobL+(c+1)*12288,tid); cp_commit(); }
            u32 bb=smb+RBB+(c&1)*24576;
            u32 bh[4][4], bl[4][4];
#pragma unroll
            for(int j=0;j<4;j++){
                u32 ba=bb+boff+j*768;
                ldm4(bh[j],ba);
                ldm4(bl[j],ba+12288);
            }
            u32 au=(u32)(((2*c+(g2>>1))^row)<<4);
            u32 ah[2][4], al[2][4];
            ldm4(ah[0],smb+RBH+arow+au);
            ldm4(al[0],smb+RBL+arow+au);
            ldm4(ah[1],smb+RBH+arow+8192u+au);
            ldm4(al[1],smb+RBL+arow+8192u+au);
#pragma unroll
            for(int mt=0;mt<2;mt++){
#pragma unroll
                for(int p=0;p<3;p++){
                    const u32* A=(p==2)?al[mt]:ah[mt];
#pragma unroll
                    for(int nt=0;nt<8;nt++){
                        const u32* B=(p==1)?bl[nt>>1]:bh[nt>>1];
                        mma16816(acc[mt][nt],A,B[(nt&1)*2],B[(nt&1)*2+1]);
                    }
                }
            }
        }
        __syncthreads();
        if(L==0){
#pragma unroll
            for(int mt=0;mt<2;mt++){
                int r0=m0+mt*16+(lane>>2), r1=r0+8;
#pragma unroll
                for(int nt=0;nt<8;nt++){
                    int n=n0+nt*8+(lane&3)*2;
                    float v0=softplusf(acc[mt][nt][0]+bias[n]);
                    float v1=softplusf(acc[mt][nt][1]+bias[n+1]);
                    float v2=softplusf(acc[mt][nt][2]+bias[n]);
                    float v3=softplusf(acc[mt][nt][3]+bias[n+1]);
                    u32 h0,l0,h1,l1;
                    splitpk(v0,v1,h0,l0);
                    splitpk(v2,v3,h1,l1);
                    int o0=r0*512+(((n>>3)^(r0&7))<<4)+(n&7)*2;
                    int o1=r1*512+(((n>>3)^(r1&7))<<4)+(n&7)*2;
                    *(u32*)(sm+RBH+o0)=h0; *(u32*)(sm+RBL+o0)=l0;
                    *(u32*)(sm+RBH+o1)=h1; *(u32*)(sm+RBL+o1)=l1;
                }
            }
        } else {
#pragma unroll
            for(int mt=0;mt<2;mt++){
                float s0=0.f,s1=0.f;
#pragma unroll
                for(int nt=0;nt<8;nt++){
                    int n=n0+nt*8+(lane&3)*2;
                    s0+=softplusf(acc[mt][nt][0]+bias[n])*s_w4[n]
                       +softplusf(acc[mt][nt][1]+bias[n+1])*s_w4[n+1];
                    s1+=softplusf(acc[mt][nt][2]+bias[n])*s_w4[n]
                       +softplusf(acc[mt][nt][3]+bias[n+1])*s_w4[n+1];
                }
                s0+=__shfl_xor_sync(0xffffffffu,s0,1); s0+=__shfl_xor_sync(0xffffffffu,s0,2);
                s1+=__shfl_xor_sync(0xffffffffu,s1,1); s1+=__shfl_xor_sync(0xffffffffu,s1,2);
                if((lane&3)==0){
                    int r0=m0+mt*16+(lane>>2);
                    s_red[r0*4+nw]=s0;
                    s_red[(r0+8)*4+nw]=s1;
                }
            }
            __syncthreads();
            if(tid<64) s_f[tid]=s_red[tid*4]+s_red[tid*4+1]+s_red[tid*4+2]+s_red[tid*4+3]+b4v;
        }
        __syncthreads();
    }
}

__global__ void __launch_bounds__(256,1)
k_refine(const float* __restrict__ ray0,const float* __restrict__ rdir,
         const float* __restrict__ W1,const float* __restrict__ b1,
         const float* __restrict__ b2,const float* __restrict__ b3,
         const float* __restrict__ W4,const float* __restrict__ b4,
         float* __restrict__ out){
    extern __shared__ char sm[];
    __shared__ float s_bias2[256],s_bias3[256],s_w4[256],s_red[256];
    __shared__ float s_o[192],s_rd[192];
    __shared__ float s_dl[64],s_fl[64],s_dh[64],s_fh[64],s_dp[64],s_f[64],s_f0[64],s_fm[64];
    __shared__ float s_a[64],s_b[64];
    __shared__ int s_mask[64];
    int tid=threadIdx.x, rbase=blockIdx.x*64;
    u32 smb=smem_u32(sm);
    s_bias2[tid]=b2[tid]; s_bias3[tid]=b3[tid]; s_w4[tid]=W4[tid];
    float b4v=b4[0];
    if(tid<64){
        int r=rbase+tid;
        s_o[tid]=ray0[3*r]; s_o[64+tid]=ray0[3*r+1]; s_o[128+tid]=ray0[3*r+2];
        s_rd[tid]=rdir[3*r]; s_rd[64+tid]=rdir[3*r+1]; s_rd[128+tid]=rdir[3*r+2];
        s_a[tid]=g_a[r]; s_b[tid]=g_b[r];
    }
    // scan proposal values (reuse A-plane smem as staging)
    float* vbuf=(float*)sm;
    for(int i=tid;i<64*SSAMP;i+=256) vbuf[i]=g_val[rbase*SSAMP+i];
    __syncthreads();
    if(tid<64){
        const float* v=vbuf+tid*SSAMP;
        float best=1e30f; int bidx=0;
        for(int s=0;s<SSAMP;s++){
            float c;
            if(s<SSAMP-1){ float pr=v[s]*v[s+1];
                float sg=(pr>0.f)?1.f:((pr<0.f)?-1.f:0.f); c=sg*(float)(SSAMP-s); }
            else c=1.f;
            if(c<best){ best=c; bidx=s; }
        }
        float fl=v[bidx];
        int ihi=bidx+1; if(ihi>SSAMP-1) ihi=SSAMP-1;
        float dl=s_a[tid]+(float)bidx*s_b[tid];
        float dh=s_a[tid]+(float)ihi*s_b[tid];
        float fh=v[ihi];
        s_mask[tid]=(best<0.f)&&(fl<0.f)&&(v[0]<0.f);
        s_dl[tid]=dl; s_fl[tid]=fl; s_dh[tid]=dh; s_fh[tid]=fh;
        s_dp[tid]=secantf(dl,fl,dh,fh);
    }
    __syncthreads();
    for(int it=0;it<8;it++){
        eval_mma(sm,smb,tid,0.f,W1,b1,s_o,s_rd,s_dp,s_bias2,s_bias3,s_w4,b4v,s_red,s_f);
        if(tid<64){
            float fm=s_f[tid];
            float dl=s_dl[tid],fl=s_fl[tid],dh=s_dh[tid],fh=s_fh[tid],dp=s_dp[tid];
            if(fm<0.f){ dl=dp; fl=fm; } else { dh=dp; fh=fm; }
            s_dl[tid]=dl; s_fl[tid]=fl; s_dh[tid]=dh; s_fh[tid]=fh;
            s_dp[tid]=secantf(dl,fl,dh,fh);
        }
        __syncthreads();
    }
    eval_mma(sm,smb,tid,0.f,W1,b1,s_o,s_rd,s_dp,s_bias2,s_bias3,s_w4,b4v,s_red,s_f);
    if(tid<64) s_f0[tid]=s_f[tid];
    __syncthreads();
    eval_mma(sm,smb,tid,-FDE,W1,b1,s_o,s_rd,s_dp,s_bias2,s_bias3,s_w4,b4v,s_red,s_f);
    if(tid<64) s_fm[tid]=s_f[tid];
    __syncthreads();
    eval_mma(sm,smb,tid,FDE,W1,b1,s_o,s_rd,s_dp,s_bias2,s_bias3,s_w4,b4v,s_red,s_f);
    if(tid<64){
        float df=(s_f[tid]-s_fm[tid])*(0.5f/FDE);
        if(fabsf(df)<1e-6f) df=(df<0.f)?-1e-6f:1e-6f;
        float dout=s_dp[tid]-s_f0[tid]/df;
        out[rbase+tid]=s_mask[tid]?dout:0.f;
    }
}

extern "C" void kernel_launch(void* const* d_in,const int* in_sizes,int n_in,
                              void* d_out,int out_size){
    const float* ray0=(const float*)d_in[0];
    const float* rdir=(const float*)d_in[1];
    const float* W1=(const float*)d_in[2];
    const float* b1=(const float*)d_in[3];
    const float* W2=(const float*)d_in[4];
    const float* b2=(const float*)d_in[5];
    const float* W3=(const float*)d_in[6];
    const float* b3=(const float*)d_in[7];
    const float* W4=(const float*)d_in[8];
    const float* b4=(const float*)d_in[9];
    float* out=(float*)d_out;
    const int smemBig=180224;
    const int smemRef=114688;
    cudaFuncSetAttribute(k_big,cudaFuncAttributeMaxDynamicSharedMemorySize,smemBig);
    cudaFuncSetAttribute(k_refine,cudaFuncAttributeMaxDynamicSharedMemorySize,smemRef);
    k_prep<<<512,256>>>(W2,W3);
    k_setup<<<(NRAYS+255)/256,256>>>(ray0,rdir);
    k_big<<<NRAYS,256,smemBig>>>(ray0,rdir,W1,b1,b2,b3,W4,b4);
    k_refine<<<NRAYS/64,256,smemRef>>>(ray0,rdir,W1,b1,b2,b3,W4,b4,out);
}

// round 10
// speedup vs baseline: 3.0299x; 1.6586x over previous
#include <cuda_runtime.h>
#include <cuda_bf16.h>
#include <cstdint>
typedef unsigned long long u64;
typedef unsigned int u32;

#define NRAYS 8192
#define SSAMP 128
#define P_DIST 0.55f
#define CUBE_EPS 1e-6f
#define FDE 2e-3f

__device__ float g_val[NRAYS * SSAMP];
__device__ float g_a[NRAYS];
__device__ float g_b[NRAYS];
// [layer][hi/lo]: 16 chunks x (256 n-rows x 48B pitch, 16 k bf16) = 196608 B
__device__ __align__(128) unsigned char g_WB[2][2][196608];

// ---- helpers ----
__device__ __forceinline__ u32 smem_u32(const void* p){ return (u32)__cvta_generic_to_shared(p); }
__device__ __forceinline__ float softplusf(float x){
    return fmaxf(x,0.f)+__logf(1.f+__expf(-fabsf(x)));
}
__device__ __forceinline__ float secantf(float dl,float fl,float dh,float fh){
    float den=fh-fl; if(fabsf(den)<1e-12f) den=1e-12f; return -fl*(dh-dl)/den+dl; }
__device__ __forceinline__ void cp16(u32 dst,const void* src){ asm volatile("cp.async.cg.shared.global [%0],[%1],16;"::"r"(dst),"l"(src):"memory"); }
__device__ __forceinline__ void cp_commit(){ asm volatile("cp.async.commit_group;":::"memory"); }
__device__ __forceinline__ void cp_wait0(){ asm volatile("cp.async.wait_group 0;":::"memory"); }

__device__ __forceinline__ void ldm4(u32* r,u32 a){
    asm volatile("ldmatrix.sync.aligned.m8n8.x4.shared.b16 {%0,%1,%2,%3},[%4];"
        :"=r"(r[0]),"=r"(r[1]),"=r"(r[2]),"=r"(r[3]):"r"(a)); }
__device__ __forceinline__ void mma16816(float* d,const u32* a,u32 b0,u32 b1){
    asm volatile("mma.sync.aligned.m16n8k16.row.col.f32.bf16.bf16.f32 "
        "{%0,%1,%2,%3},{%4,%5,%6,%7},{%8,%9},{%0,%1,%2,%3};"
        :"+f"(d[0]),"+f"(d[1]),"+f"(d[2]),"+f"(d[3])
        :"r"(a[0]),"r"(a[1]),"r"(a[2]),"r"(a[3]),"r"(b0),"r"(b1)); }
__device__ __forceinline__ void splitpk(float x,float y,u32&h,u32&l){
    __nv_bfloat16 hx=__float2bfloat16_rn(x), hy=__float2bfloat16_rn(y);
    __nv_bfloat16 lx=__float2bfloat16_rn(x-__bfloat162float(hx));
    __nv_bfloat16 ly=__float2bfloat16_rn(y-__bfloat162float(hy));
    h=((u32)*(unsigned short*)&hx)|(((u32)*(unsigned short*)&hy)<<16);
    l=((u32)*(unsigned short*)&lx)|(((u32)*(unsigned short*)&ly)<<16);
}
__device__ __forceinline__ u32 pkbf(float x,float y){
    __nv_bfloat16 hx=__float2bfloat16_rn(x), hy=__float2bfloat16_rn(y);
    return ((u32)*(unsigned short*)&hx)|(((u32)*(unsigned short*)&hy)<<16);
}

// ---- k_prep ----
__global__ void k_prep(const float* __restrict__ W2,const float* __restrict__ W3){
    int idx=blockIdx.x*blockDim.x+threadIdx.x;
    int layer=idx>>16, e=idx&65535;
    const float* W=layer?W3:W2;
    int k=e>>8, n=e&255;
    float w=W[e];
    __nv_bfloat16 hi=__float2bfloat16_rn(w);
    __nv_bfloat16 lo=__float2bfloat16_rn(w-__bfloat162float(hi));
    int c=k>>4, kk=k&15;
    size_t off=(size_t)c*12288+(size_t)n*48+(size_t)kk*2;
    *(__nv_bfloat16*)(g_WB[layer][0]+off)=hi;
    *(__nv_bfloat16*)(g_WB[layer][1]+off)=lo;
}

// ---- cube intersection ----
__global__ void k_setup(const float* __restrict__ ray0,const float* __restrict__ rdir){
    int r=blockIdx.x*blockDim.x+threadIdx.x; if(r>=NRAYS) return;
    float o0=ray0[3*r],o1=ray0[3*r+1],o2=ray0[3*r+2];
    float r0=rdir[3*r],r1=rdir[3*r+1],r2=rdir[3*r+2];
    float ov[3]={o0,o1,o2},rv[3]={r0,r1,r2},t2[2]={0.f,0.f};
    int cnt=0; float rn=sqrtf(r0*r0+r1*r1+r2*r2);
#pragma unroll
    for(int i=0;i<6;i++){
        int ax=i%3; float pv=(i<3)?P_DIST:-P_DIST;
        float den=rv[ax]; if(fabsf(den)<1e-9f) den=1e-9f;
        float t=(pv-ov[ax])/den;
        float q0=o0+t*r0,q1=o1+t*r1,q2=o2+t*r2;
        bool ins=(fabsf(q0)<=P_DIST+CUBE_EPS)&&(fabsf(q1)<=P_DIST+CUBE_EPS)&&(fabsf(q2)<=P_DIST+CUBE_EPS);
        if(ins){ if(cnt<2){ float e0=q0-o0,e1=q1-o1,e2=q2-o2;
                t2[cnt]=sqrtf(e0*e0+e1*e1+e2*e2)/rn; } cnt++; }
    }
    float a,b;
    if(cnt==2){ float lo=fminf(t2[0],t2[1]),hi=fmaxf(t2[0],t2[1]); a=lo; b=(hi-lo)*(1.f/127.f); }
    else { a=0.f; b=2.4f/127.f; }
    g_a[r]=a; g_b[r]=b;
}

// ---- stageB: 24KB weight chunk (hi+lo) for k_refine ----
__device__ __forceinline__ void stageB(char* dst,const unsigned char* sH,const unsigned char* sL,int tid){
    u32 d=smem_u32(dst);
#pragma unroll
    for(int j=0;j<3;j++){ int u=tid+j*256; cp16(d+u*16,sH+u*16); }
#pragma unroll
    for(int j=0;j<3;j++){ int u=tid+j*256; cp16(d+12288+u*16,sL+u*16); }
}
// ---- stageBh: 12KB hi-only chunk for k_big ----
__device__ __forceinline__ void stageBh(char* dst,const unsigned char* sH,int tid){
    u32 d=smem_u32(dst);
#pragma unroll
    for(int j=0;j<3;j++){ int u=tid+j*256; cp16(d+u*16,sH+u*16); }
}

// ---- k_big: one ray/CTA, 8 warps 2m x 4n, SINGLE-product bf16 mma ----
// smem: A_hi 64KB @0, Bbuf 2x12288 @65536  (total 90112)
#define ABH 0
#define BBF 65536
__global__ void __launch_bounds__(256,1)
k_big(const float* __restrict__ ray0,const float* __restrict__ rdir,
      const float* __restrict__ W1,const float* __restrict__ b1,
      const float* __restrict__ b2,const float* __restrict__ b3,
      const float* __restrict__ W4,const float* __restrict__ b4){
    extern __shared__ char sm[];
    __shared__ float s_bias[256], s_w4[256], s_red[512], s_c[512];
    int tid=threadIdx.x, lane=tid&31, warp=tid>>5, ray=blockIdx.x;
    u32 smb=smem_u32(sm);

    float a=g_a[ray], st=g_b[ray];
    float ox=ray0[ray*3],oy=ray0[ray*3+1],oz=ray0[ray*3+2];
    float dx=rdir[ray*3],dy=rdir[ray*3+1],dz=rdir[ray*3+2];
    s_c[2*tid]  =fmaf(ox,W1[tid],fmaf(oy,W1[256+tid],fmaf(oz,W1[512+tid],b1[tid])));
    s_c[2*tid+1]=fmaf(dx,W1[tid],fmaf(dy,W1[256+tid],dz*W1[512+tid]));
    __syncthreads();
    {
        int m=tid&127, kh=tid>>7;
        float d=a+(float)m*st;
#pragma unroll 4
        for(int j=0;j<128;j+=2){
            int k=kh*128+j;
            float2 ca=*(float2*)(s_c+2*k);
            float2 cb=*(float2*)(s_c+2*k+2);
            float v0=softplusf(fmaf(d,ca.y,ca.x));
            float v1=softplusf(fmaf(d,cb.y,cb.x));
            int off=m*512+((((k>>3))^(m&7))<<4)+((k&7)<<1);
            *(u32*)(sm+ABH+off)=pkbf(v0,v1);
        }
    }

    int g2=lane>>3, row=lane&7;
    int mw=warp&1, nw=warp>>1;
    int m0=mw*64, n0=nw*64;
    u32 arow=(u32)((m0+(g2&1)*8+row)*512);
    u32 boff=(u32)((n0+(g2>>1)*8+row)*48+(g2&1)*16);

    for(int L=0;L<2;L++){
        s_bias[tid]=L?b3[tid]:b2[tid];
        if(L) s_w4[tid]=W4[tid];
        const unsigned char* blobH=g_WB[L][0];
        float acc[4][8][4];
#pragma unroll
        for(int i=0;i<4;i++)
#pragma unroll
            for(int j=0;j<8;j++){ acc[i][j][0]=0.f; acc[i][j][1]=0.f; acc[i][j][2]=0.f; acc[i][j][3]=0.f; }
        stageBh(sm+BBF,blobH,tid); cp_commit();
        for(int c=0;c<16;c++){
            cp_wait0();
            __syncthreads();
            if(c<15){ stageBh(sm+BBF+((c+1)&1)*12288,blobH+(c+1)*12288,tid); cp_commit(); }
            u32 bb=smb+BBF+(c&1)*12288;
            u32 bh[4][4];
#pragma unroll
            for(int j=0;j<4;j++) ldm4(bh[j],bb+boff+j*768);
            u32 au=(u32)(((2*c+(g2>>1))^row)<<4);
            u32 ah[2][4];
            ldm4(ah[0],smb+ABH+arow+au);
#pragma unroll
            for(int mt=0;mt<4;mt++){
                int cur=mt&1;
                if(mt<3) ldm4(ah[cur^1],smb+ABH+arow+(u32)((mt+1)*8192)+au);
#pragma unroll
                for(int nt=0;nt<8;nt++){
                    const u32* B=bh[nt>>1];
                    mma16816(acc[mt][nt],ah[cur],B[(nt&1)*2],B[(nt&1)*2+1]);
                }
            }
        }
        __syncthreads();
        if(L==0){
#pragma unroll
            for(int mt=0;mt<4;mt++){
                int r0=m0+mt*16+(lane>>2), r1=r0+8;
#pragma unroll
                for(int nt=0;nt<8;nt++){
                    int n=n0+nt*8+(lane&3)*2;
                    float v0=softplusf(acc[mt][nt][0]+s_bias[n]);
                    float v1=softplusf(acc[mt][nt][1]+s_bias[n+1]);
                    float v2=softplusf(acc[mt][nt][2]+s_bias[n]);
                    float v3=softplusf(acc[mt][nt][3]+s_bias[n+1]);
                    int o0=r0*512+(((n>>3)^(r0&7))<<4)+(n&7)*2;
                    int o1=r1*512+(((n>>3)^(r1&7))<<4)+(n&7)*2;
                    *(u32*)(sm+ABH+o0)=pkbf(v0,v1);
                    *(u32*)(sm+ABH+o1)=pkbf(v2,v3);
                }
            }
        } else {
#pragma unroll
            for(int mt=0;mt<4;mt++){
                float s0=0.f,s1=0.f;
#pragma unroll
                for(int nt=0;nt<8;nt++){
                    int n=n0+nt*8+(lane&3)*2;
                    s0+=softplusf(acc[mt][nt][0]+s_bias[n])*s_w4[n]
                       +softplusf(acc[mt][nt][1]+s_bias[n+1])*s_w4[n+1];
                    s1+=softplusf(acc[mt][nt][2]+s_bias[n])*s_w4[n]
                       +softplusf(acc[mt][nt][3]+s_bias[n+1])*s_w4[n+1];
                }
                s0+=__shfl_xor_sync(0xffffffffu,s0,1); s0+=__shfl_xor_sync(0xffffffffu,s0,2);
                s1+=__shfl_xor_sync(0xffffffffu,s1,1); s1+=__shfl_xor_sync(0xffffffffu,s1,2);
                if((lane&3)==0){
                    int r0=m0+mt*16+(lane>>2);
                    s_red[r0*4+nw]=s0;
                    s_red[(r0+8)*4+nw]=s1;
                }
            }
            __syncthreads();
            if(tid<128)
                g_val[ray*SSAMP+tid]=s_red[tid*4]+s_red[tid*4+1]+s_red[tid*4+2]+s_red[tid*4+3]+b4[0];
        }
        __syncthreads();
    }
}

// ======== k_refine: HMMA split-3 evals, M=64 (64 rays/CTA) — unchanged R9 ========
#define RBH 0
#define RBL 32768
#define RBB 65536   // 2 x 24576
__device__ __forceinline__ void eval_mma(char* sm,u32 smb,int tid,float delta,
    const float* __restrict__ W1,const float* __restrict__ b1,
    const float* s_o,const float* s_rd,const float* s_dp,
    const float* s_bias2,const float* s_bias3,const float* s_w4,float b4v,
    float* s_red,float* s_f){
    int lane=tid&31, warp=tid>>5;
    {
        int m=tid&63, kg=tid>>6;
        float d=s_dp[m]+delta;
        float px=s_o[m]+d*s_rd[m], py=s_o[64+m]+d*s_rd[64+m], pz=s_o[128+m]+d*s_rd[128+m];
#pragma unroll 4
        for(int j=0;j<64;j+=2){
            int k=kg*64+j;
            float z0=fmaf(px,W1[k],fmaf(py,W1[256+k],fmaf(pz,W1[512+k],b1[k])));
            float z1=fmaf(px,W1[k+1],fmaf(py,W1[257+k],fmaf(pz,W1[513+k],b1[k+1])));
            float v0=softplusf(z0), v1=softplusf(z1);
            u32 h,l; splitpk(v0,v1,h,l);
            int off=m*512+((((k>>3))^(m&7))<<4)+((k&7)<<1);
            *(u32*)(sm+RBH+off)=h;
            *(u32*)(sm+RBL+off)=l;
        }
    }
    int g2=lane>>3, row=lane&7;
    int mw=warp&1, nw=warp>>1;
    int m0=mw*32, n0=nw*64;
    u32 arow=(u32)((m0+(g2&1)*8+row)*512);
    u32 boff=(u32)((n0+(g2>>1)*8+row)*48+(g2&1)*16);

    for(int L=0;L<2;L++){
        const float* bias=L?s_bias3:s_bias2;
        const unsigned char* blobH=g_WB[L][0];
        const unsigned char* blobL=g_WB[L][1];
        float acc[2][8][4];
#pragma unroll
        for(int i=0;i<2;i++)
#pragma unroll
            for(int j=0;j<8;j++){ acc[i][j][0]=0.f; acc[i][j][1]=0.f; acc[i][j][2]=0.f; acc[i][j][3]=0.f; }
        stageB(sm+RBB,blobH,blobL,tid); cp_commit();
        for(int c=0;c<16;c++){
            cp_wait0();
            __syncthreads();
            if(c<15){ stageB(sm+RBB+((c+1)&1)*24576,blobH+(c+1)*12288,blobL+(c+1)*12288,tid); cp_commit(); }
            u32 bb=smb+RBB+(c&1)*24576;
            u32 bh[4][4], bl[4][4];
#pragma unroll
            for(int j=0;j<4;j++){
                u32 ba=bb+boff+j*768;
                ldm4(bh[j],ba);
                ldm4(bl[j],ba+12288);
            }
            u32 au=(u32)(((2*c+(g2>>1))^row)<<4);
            u32 ah[2][4], al[2][4];
            ldm4(ah[0],smb+RBH+arow+au);
            ldm4(al[0],smb+RBL+arow+au);
            ldm4(ah[1],smb+RBH+arow+8192u+au);
            ldm4(al[1],smb+RBL+arow+8192u+au);
#pragma unroll
            for(int mt=0;mt<2;mt++){
#pragma unroll
                for(int p=0;p<3;p++){
                    const u32* A=(p==2)?al[mt]:ah[mt];
#pragma unroll
                    for(int nt=0;nt<8;nt++){
                        const u32* B=(p==1)?bl[nt>>1]:bh[nt>>1];
                        mma16816(acc[mt][nt],A,B[(nt&1)*2],B[(nt&1)*2+1]);
                    }
                }
            }
        }
        __syncthreads();
        if(L==0){
#pragma unroll
            for(int mt=0;mt<2;mt++){
                int r0=m0+mt*16+(lane>>2), r1=r0+8;
#pragma unroll
                for(int nt=0;nt<8;nt++){
                    int n=n0+nt*8+(lane&3)*2;
                    float v0=softplusf(acc[mt][nt][0]+bias[n]);
                    float v1=softplusf(acc[mt][nt][1]+bias[n+1]);
                    float v2=softplusf(acc[mt][nt][2]+bias[n]);
                    float v3=softplusf(acc[mt][nt][3]+bias[n+1]);
                    u32 h0,l0,h1,l1;
                    splitpk(v0,v1,h0,l0);
                    splitpk(v2,v3,h1,l1);
                    int o0=r0*512+(((n>>3)^(r0&7))<<4)+(n&7)*2;
                    int o1=r1*512+(((n>>3)^(r1&7))<<4)+(n&7)*2;
                    *(u32*)(sm+RBH+o0)=h0; *(u32*)(sm+RBL+o0)=l0;
                    *(u32*)(sm+RBH+o1)=h1; *(u32*)(sm+RBL+o1)=l1;
                }
            }
        } else {
#pragma unroll
            for(int mt=0;mt<2;mt++){
                float s0=0.f,s1=0.f;
#pragma unroll
                for(int nt=0;nt<8;nt++){
                    int n=n0+nt*8+(lane&3)*2;
                    s0+=softplusf(acc[mt][nt][0]+bias[n])*s_w4[n]
                       +softplusf(acc[mt][nt][1]+bias[n+1])*s_w4[n+1];
                    s1+=softplusf(acc[mt][nt][2]+bias[n])*s_w4[n]
                       +softplusf(acc[mt][nt][3]+bias[n+1])*s_w4[n+1];
                }
                s0+=__shfl_xor_sync(0xffffffffu,s0,1); s0+=__shfl_xor_sync(0xffffffffu,s0,2);
                s1+=__shfl_xor_sync(0xffffffffu,s1,1); s1+=__shfl_xor_sync(0xffffffffu,s1,2);
                if((lane&3)==0){
                    int r0=m0+mt*16+(lane>>2);
                    s_red[r0*4+nw]=s0;
                    s_red[(r0+8)*4+nw]=s1;
                }
            }
            __syncthreads();
            if(tid<64) s_f[tid]=s_red[tid*4]+s_red[tid*4+1]+s_red[tid*4+2]+s_red[tid*4+3]+b4v;
        }
        __syncthreads();
    }
}

__global__ void __launch_bounds__(256,1)
k_refine(const float* __restrict__ ray0,const float* __restrict__ rdir,
         const float* __restrict__ W1,const float* __restrict__ b1,
         const float* __restrict__ b2,const float* __restrict__ b3,
         const float* __restrict__ W4,const float* __restrict__ b4,
         float* __restrict__ out){
    extern __shared__ char sm[];
    __shared__ float s_bias2[256],s_bias3[256],s_w4[256],s_red[256];
    __shared__ float s_o[192],s_rd[192];
    __shared__ float s_dl[64],s_fl[64],s_dh[64],s_fh[64],s_dp[64],s_f[64],s_f0[64],s_fm[64];
    __shared__ float s_a[64],s_b[64];
    __shared__ int s_mask[64];
    int tid=threadIdx.x, rbase=blockIdx.x*64;
    u32 smb=smem_u32(sm);
    s_bias2[tid]=b2[tid]; s_bias3[tid]=b3[tid]; s_w4[tid]=W4[tid];
    float b4v=b4[0];
    if(tid<64){
        int r=rbase+tid;
        s_o[tid]=ray0[3*r]; s_o[64+tid]=ray0[3*r+1]; s_o[128+tid]=ray0[3*r+2];
        s_rd[tid]=rdir[3*r]; s_rd[64+tid]=rdir[3*r+1]; s_rd[128+tid]=rdir[3*r+2];
        s_a[tid]=g_a[r]; s_b[tid]=g_b[r];
    }
    float* vbuf=(float*)sm;
    for(int i=tid;i<64*SSAMP;i+=256) vbuf[i]=g_val[rbase*SSAMP+i];
    __syncthreads();
    if(tid<64){
        const float* v=vbuf+tid*SSAMP;
        float best=1e30f; int bidx=0;
        for(int s=0;s<SSAMP;s++){
            float c;
            if(s<SSAMP-1){ float pr=v[s]*v[s+1];
                float sg=(pr>0.f)?1.f:((pr<0.f)?-1.f:0.f); c=sg*(float)(SSAMP-s); }
            else c=1.f;
            if(c<best){ best=c; bidx=s; }
        }
        float fl=v[bidx];
        int ihi=bidx+1; if(ihi>SSAMP-1) ihi=SSAMP-1;
        float dl=s_a[tid]+(float)bidx*s_b[tid];
        float dh=s_a[tid]+(float)ihi*s_b[tid];
        float fh=v[ihi];
        s_mask[tid]=(best<0.f)&&(fl<0.f)&&(v[0]<0.f);
        s_dl[tid]=dl; s_fl[tid]=fl; s_dh[tid]=dh; s_fh[tid]=fh;
        s_dp[tid]=secantf(dl,fl,dh,fh);
    }
    __syncthreads();
    for(int it=0;it<8;it++){
        eval_mma(sm,smb,tid,0.f,W1,b1,s_o,s_rd,s_dp,s_bias2,s_bias3,s_w4,b4v,s_red,s_f);
        if(tid<64){
            float fm=s_f[tid];
            float dl=s_dl[tid],fl=s_fl[tid],dh=s_dh[tid],fh=s_fh[tid],dp=s_dp[tid];
            if(fm<0.f){ dl=dp; fl=fm; } else { dh=dp; fh=fm; }
            s_dl[tid]=dl; s_fl[tid]=fl; s_dh[tid]=dh; s_fh[tid]=fh;
            s_dp[tid]=secantf(dl,fl,dh,fh);
        }
        __syncthreads();
    }
    eval_mma(sm,smb,tid,0.f,W1,b1,s_o,s_rd,s_dp,s_bias2,s_bias3,s_w4,b4v,s_red,s_f);
    if(tid<64) s_f0[tid]=s_f[tid];
    __syncthreads();
    eval_mma(sm,smb,tid,-FDE,W1,b1,s_o,s_rd,s_dp,s_bias2,s_bias3,s_w4,b4v,s_red,s_f);
    if(tid<64) s_fm[tid]=s_f[tid];
    __syncthreads();
    eval_mma(sm,smb,tid,FDE,W1,b1,s_o,s_rd,s_dp,s_bias2,s_bias3,s_w4,b4v,s_red,s_f);
    if(tid<64){
        float df=(s_f[tid]-s_fm[tid])*(0.5f/FDE);
        if(fabsf(df)<1e-6f) df=(df<0.f)?-1e-6f:1e-6f;
        float dout=s_dp[tid]-s_f0[tid]/df;
        out[rbase+tid]=s_mask[tid]?dout:0.f;
    }
}

extern "C" void kernel_launch(void* const* d_in,const int* in_sizes,int n_in,
                              void* d_out,int out_size){
    const float* ray0=(const float*)d_in[0];
    const float* rdir=(const float*)d_in[1];
    const float* W1=(const float*)d_in[2];
    const float* b1=(const float*)d_in[3];
    const float* W2=(const float*)d_in[4];
    const float* b2=(const float*)d_in[5];
    const float* W3=(const float*)d_in[6];
    const float* b3=(const float*)d_in[7];
    const float* W4=(const float*)d_in[8];
    const float* b4=(const float*)d_in[9];
    float* out=(float*)d_out;
    const int smemBig=90112;
    const int smemRef=114688;
    cudaFuncSetAttribute(k_big,cudaFuncAttributeMaxDynamicSharedMemorySize,smemBig);
    cudaFuncSetAttribute(k_refine,cudaFuncAttributeMaxDynamicSharedMemorySize,smemRef);
    k_prep<<<512,256>>>(W2,W3);
    k_setup<<<(NRAYS+255)/256,256>>>(ray0,rdir);
    k_big<<<NRAYS,256,smemBig>>>(ray0,rdir,W1,b1,b2,b3,W4,b4);
    k_refine<<<NRAYS/64,256,smemRef>>>(ray0,rdir,W1,b1,b2,b3,W4,b4,out);
}

// round 13
// speedup vs baseline: 4.1960x; 1.3848x over previous
#include <cuda_runtime.h>
#include <cuda_bf16.h>
#include <cstdint>
typedef unsigned long long u64;
typedef unsigned int u32;

#define NRAYS 8192
#define SSAMP 128
#define P_DIST 0.55f
#define CUBE_EPS 1e-6f
#define FDE 2e-3f

__device__ float g_val[NRAYS * SSAMP];
__device__ float g_a[NRAYS];
__device__ float g_b[NRAYS];
// [layer][hi/lo]: 16 chunks x (256 n-rows x 48B pitch, 16 k bf16) = 196608 B
__device__ __align__(128) unsigned char g_WB[2][2][196608];

// ---- helpers ----
__device__ __forceinline__ u32 smem_u32(const void* p){ return (u32)__cvta_generic_to_shared(p); }
__device__ __forceinline__ float softplusf(float x){
    return fmaxf(x,0.f)+__logf(1.f+__expf(-fabsf(x)));
}
__device__ __forceinline__ float secantf(float dl,float fl,float dh,float fh){
    float den=fh-fl; if(fabsf(den)<1e-12f) den=1e-12f; return -fl*(dh-dl)/den+dl; }
__device__ __forceinline__ void cp16(u32 dst,const void* src){ asm volatile("cp.async.cg.shared.global [%0],[%1],16;"::"r"(dst),"l"(src):"memory"); }
__device__ __forceinline__ void cp_commit(){ asm volatile("cp.async.commit_group;":::"memory"); }
__device__ __forceinline__ void cp_wait0(){ asm volatile("cp.async.wait_group 0;":::"memory"); }

__device__ __forceinline__ void ldm4(u32* r,u32 a){
    asm volatile("ldmatrix.sync.aligned.m8n8.x4.shared.b16 {%0,%1,%2,%3},[%4];"
        :"=r"(r[0]),"=r"(r[1]),"=r"(r[2]),"=r"(r[3]):"r"(a)); }
__device__ __forceinline__ void mma16816(float* d,const u32* a,u32 b0,u32 b1){
    asm volatile("mma.sync.aligned.m16n8k16.row.col.f32.bf16.bf16.f32 "
        "{%0,%1,%2,%3},{%4,%5,%6,%7},{%8,%9},{%0,%1,%2,%3};"
        :"+f"(d[0]),"+f"(d[1]),"+f"(d[2]),"+f"(d[3])
        :"r"(a[0]),"r"(a[1]),"r"(a[2]),"r"(a[3]),"r"(b0),"r"(b1)); }
__device__ __forceinline__ void splitpk(float x,float y,u32&h,u32&l){
    __nv_bfloat16 hx=__float2bfloat16_rn(x), hy=__float2bfloat16_rn(y);
    __nv_bfloat16 lx=__float2bfloat16_rn(x-__bfloat162float(hx));
    __nv_bfloat16 ly=__float2bfloat16_rn(y-__bfloat162float(hy));
    h=((u32)*(unsigned short*)&hx)|(((u32)*(unsigned short*)&hy)<<16);
    l=((u32)*(unsigned short*)&lx)|(((u32)*(unsigned short*)&ly)<<16);
}
__device__ __forceinline__ u32 pkbf(float x,float y){
    __nv_bfloat16 hx=__float2bfloat16_rn(x), hy=__float2bfloat16_rn(y);
    return ((u32)*(unsigned short*)&hx)|(((u32)*(unsigned short*)&hy)<<16);
}

// ---- k_prep ----
__global__ void k_prep(const float* __restrict__ W2,const float* __restrict__ W3){
    int idx=blockIdx.x*blockDim.x+threadIdx.x;
    int layer=idx>>16, e=idx&65535;
    const float* W=layer?W3:W2;
    int k=e>>8, n=e&255;
    float w=W[e];
    __nv_bfloat16 hi=__float2bfloat16_rn(w);
    __nv_bfloat16 lo=__float2bfloat16_rn(w-__bfloat162float(hi));
    int c=k>>4, kk=k&15;
    size_t off=(size_t)c*12288+(size_t)n*48+(size_t)kk*2;
    *(__nv_bfloat16*)(g_WB[layer][0]+off)=hi;
    *(__nv_bfloat16*)(g_WB[layer][1]+off)=lo;
}

// ---- cube intersection ----
__global__ void k_setup(const float* __restrict__ ray0,const float* __restrict__ rdir){
    int r=blockIdx.x*blockDim.x+threadIdx.x; if(r>=NRAYS) return;
    float o0=ray0[3*r],o1=ray0[3*r+1],o2=ray0[3*r+2];
    float r0=rdir[3*r],r1=rdir[3*r+1],r2=rdir[3*r+2];
    float ov[3]={o0,o1,o2},rv[3]={r0,r1,r2},t2[2]={0.f,0.f};
    int cnt=0; float rn=sqrtf(r0*r0+r1*r1+r2*r2);
#pragma unroll
    for(int i=0;i<6;i++){
        int ax=i%3; float pv=(i<3)?P_DIST:-P_DIST;
        float den=rv[ax]; if(fabsf(den)<1e-9f) den=1e-9f;
        float t=(pv-ov[ax])/den;
        float q0=o0+t*r0,q1=o1+t*r1,q2=o2+t*r2;
        bool ins=(fabsf(q0)<=P_DIST+CUBE_EPS)&&(fabsf(q1)<=P_DIST+CUBE_EPS)&&(fabsf(q2)<=P_DIST+CUBE_EPS);
        if(ins){ if(cnt<2){ float e0=q0-o0,e1=q1-o1,e2=q2-o2;
                t2[cnt]=sqrtf(e0*e0+e1*e1+e2*e2)/rn; } cnt++; }
    }
    float a,b;
    if(cnt==2){ float lo=fminf(t2[0],t2[1]),hi=fmaxf(t2[0],t2[1]); a=lo; b=(hi-lo)*(1.f/127.f); }
    else { a=0.f; b=2.4f/127.f; }
    g_a[r]=a; g_b[r]=b;
}

// ---- staging ----
__device__ __forceinline__ void stageB(char* dst,const unsigned char* sH,const unsigned char* sL,int tid){
    u32 d=smem_u32(dst);
#pragma unroll
    for(int j=0;j<3;j++){ int u=tid+j*256; cp16(d+u*16,sH+u*16); }
#pragma unroll
    for(int j=0;j<3;j++){ int u=tid+j*256; cp16(d+12288+u*16,sL+u*16); }
}
__device__ __forceinline__ void stageBh(char* dst,const unsigned char* sH,int tid){
    u32 d=smem_u32(dst);
#pragma unroll
    for(int j=0;j<3;j++){ int u=tid+j*256; cp16(d+u*16,sH+u*16); }
}

// ---- k_big: one ray/CTA, M-split (2 passes of M=64), 2 CTAs/SM ----
// smem: A_hi 64KB @0, Bbuf 2x12288 @65536  (total 90112)
#define ABH 0
#define BBF 65536
__global__ void __launch_bounds__(256,2)
k_big(const float* __restrict__ ray0,const float* __restrict__ rdir,
      const float* __restrict__ W1,const float* __restrict__ b1,
      const float* __restrict__ b2,const float* __restrict__ b3,
      const float* __restrict__ W4,const float* __restrict__ b4){
    extern __shared__ char sm[];
    __shared__ float s_bias[256], s_w4[256], s_red[512], s_c[512];
    int tid=threadIdx.x, lane=tid&31, warp=tid>>5, ray=blockIdx.x;
    u32 smb=smem_u32(sm);

    float a=g_a[ray], st=g_b[ray];
    float ox=ray0[ray*3],oy=ray0[ray*3+1],oz=ray0[ray*3+2];
    float dx=rdir[ray*3],dy=rdir[ray*3+1],dz=rdir[ray*3+2];
    s_c[2*tid]  =fmaf(ox,W1[tid],fmaf(oy,W1[256+tid],fmaf(oz,W1[512+tid],b1[tid])));
    s_c[2*tid+1]=fmaf(dx,W1[tid],fmaf(dy,W1[256+tid],dz*W1[512+tid]));
    __syncthreads();
    {
        int m=tid&127, kh=tid>>7;
        float d=a+(float)m*st;
#pragma unroll 4
        for(int j=0;j<128;j+=2){
            int k=kh*128+j;
            float2 ca=*(float2*)(s_c+2*k);
            float2 cb=*(float2*)(s_c+2*k+2);
            float v0=softplusf(fmaf(d,ca.y,ca.x));
            float v1=softplusf(fmaf(d,cb.y,cb.x));
            int off=m*512+((((k>>3))^(m&7))<<4)+((k&7)<<1);
            *(u32*)(sm+ABH+off)=pkbf(v0,v1);
        }
    }

    int g2=lane>>3, row=lane&7;
    int mw=warp&1, nw=warp>>1;
    int n0=nw*64;
    u32 boff=(u32)((n0+(g2>>1)*8+row)*48+(g2&1)*16);

    for(int L=0;L<2;L++){
        __syncthreads();
        s_bias[tid]=L?b3[tid]:b2[tid];
        if(L) s_w4[tid]=W4[tid];
        const unsigned char* blobH=g_WB[L][0];
        for(int mh=0;mh<2;mh++){
            int m0=mh*64+mw*32;
            u32 arow=(u32)((m0+(g2&1)*8+row)*512);
            float acc[2][8][4];
#pragma unroll
            for(int i=0;i<2;i++)
#pragma unroll
                for(int j=0;j<8;j++){ acc[i][j][0]=0.f; acc[i][j][1]=0.f; acc[i][j][2]=0.f; acc[i][j][3]=0.f; }
            __syncthreads();
            stageBh(sm+BBF,blobH,tid); cp_commit();
            for(int c=0;c<16;c++){
                cp_wait0();
                __syncthreads();
                if(c<15){ stageBh(sm+BBF+((c+1)&1)*12288,blobH+(c+1)*12288,tid); cp_commit(); }
                u32 bb=smb+BBF+(c&1)*12288;
                u32 bh[4][4];
#pragma unroll
                for(int j=0;j<4;j++) ldm4(bh[j],bb+boff+j*768);
                u32 au=(u32)(((2*c+(g2>>1))^row)<<4);
                u32 ah[2][4];
                ldm4(ah[0],smb+ABH+arow+au);
                ldm4(ah[1],smb+ABH+arow+8192u+au);
#pragma unroll
                for(int mt=0;mt<2;mt++)
#pragma unroll
                    for(int nt=0;nt<8;nt++){
                        const u32* B=bh[nt>>1];
                        mma16816(acc[mt][nt],ah[mt],B[(nt&1)*2],B[(nt&1)*2+1]);
                    }
            }
            __syncthreads();
            if(L==0){
#pragma unroll
                for(int mt=0;mt<2;mt++){
                    int r0=m0+mt*16+(lane>>2), r1=r0+8;
#pragma unroll
                    for(int nt=0;nt<8;nt++){
                        int n=n0+nt*8+(lane&3)*2;
                        float v0=softplusf(acc[mt][nt][0]+s_bias[n]);
                        float v1=softplusf(acc[mt][nt][1]+s_bias[n+1]);
                        float v2=softplusf(acc[mt][nt][2]+s_bias[n]);
                        float v3=softplusf(acc[mt][nt][3]+s_bias[n+1]);
                        int o0=r0*512+(((n>>3)^(r0&7))<<4)+(n&7)*2;
                        int o1=r1*512+(((n>>3)^(r1&7))<<4)+(n&7)*2;
                        *(u32*)(sm+ABH+o0)=pkbf(v0,v1);
                        *(u32*)(sm+ABH+o1)=pkbf(v2,v3);
                    }
                }
            } else {
#pragma unroll
                for(int mt=0;mt<2;mt++){
                    float s0=0.f,s1=0.f;
#pragma unroll
                    for(int nt=0;nt<8;nt++){
                        int n=n0+nt*8+(lane&3)*2;
                        s0+=softplusf(acc[mt][nt][0]+s_bias[n])*s_w4[n]
                           +softplusf(acc[mt][nt][1]+s_bias[n+1])*s_w4[n+1];
                        s1+=softplusf(acc[mt][nt][2]+s_bias[n])*s_w4[n]
                           +softplusf(acc[mt][nt][3]+s_bias[n+1])*s_w4[n+1];
                    }
                    s0+=__shfl_xor_sync(0xffffffffu,s0,1); s0+=__shfl_xor_sync(0xffffffffu,s0,2);
                    s1+=__shfl_xor_sync(0xffffffffu,s1,1); s1+=__shfl_xor_sync(0xffffffffu,s1,2);
                    if((lane&3)==0){
                        int r0=m0+mt*16+(lane>>2);
                        s_red[r0*4+nw]=s0;
                        s_red[(r0+8)*4+nw]=s1;
                    }
                }
            }
        }
    }
    __syncthreads();
    if(tid<128)
        g_val[ray*SSAMP+tid]=s_red[tid*4]+s_red[tid*4+1]+s_red[tid*4+2]+s_red[tid*4+3]+b4[0];
}

// ======== k_refine: HMMA evals, M=64; NP=1 for secant, NP=3 for finals ========
#define RBH 0
#define RBL 32768
#define RBB 65536   // 2 x 24576
template<int NP>
__device__ __forceinline__ void eval_mma(char* sm,u32 smb,int tid,float delta,
    const float* __restrict__ W1,const float* __restrict__ b1,
    const float* s_o,const float* s_rd,const float* s_dp,
    const float* s_bias2,const float* s_bias3,const float* s_w4,float b4v,
    float* s_red,float* s_f){
    int lane=tid&31, warp=tid>>5;
    {
        int m=tid&63, kg=tid>>6;
        float d=s_dp[m]+delta;
        float px=s_o[m]+d*s_rd[m], py=s_o[64+m]+d*s_rd[64+m], pz=s_o[128+m]+d*s_rd[128+m];
#pragma unroll 4
        for(int j=0;j<64;j+=2){
            int k=kg*64+j;
            float z0=fmaf(px,W1[k],fmaf(py,W1[256+k],fmaf(pz,W1[512+k],b1[k])));
            float z1=fmaf(px,W1[k+1],fmaf(py,W1[257+k],fmaf(pz,W1[513+k],b1[k+1])));
            float v0=softplusf(z0), v1=softplusf(z1);
            int off=m*512+((((k>>3))^(m&7))<<4)+((k&7)<<1);
            if(NP==3){
                u32 h,l; splitpk(v0,v1,h,l);
                *(u32*)(sm+RBH+off)=h;
                *(u32*)(sm+RBL+off)=l;
            } else {
                *(u32*)(sm+RBH+off)=pkbf(v0,v1);
            }
        }
    }
    int g2=lane>>3, row=lane&7;
    int mw=warp&1, nw=warp>>1;
    int m0=mw*32, n0=nw*64;
    u32 arow=(u32)((m0+(g2&1)*8+row)*512);
    u32 boff=(u32)((n0+(g2>>1)*8+row)*48+(g2&1)*16);

    for(int L=0;L<2;L++){
        const float* bias=L?s_bias3:s_bias2;
        const unsigned char* blobH=g_WB[L][0];
        const unsigned char* blobL=g_WB[L][1];
        float acc[2][8][4];
#pragma unroll
        for(int i=0;i<2;i++)
#pragma unroll
            for(int j=0;j<8;j++){ acc[i][j][0]=0.f; acc[i][j][1]=0.f; acc[i][j][2]=0.f; acc[i][j][3]=0.f; }
        if(NP==3) stageB(sm+RBB,blobH,blobL,tid); else stageBh(sm+RBB,blobH,tid);
        cp_commit();
        for(int c=0;c<16;c++){
            cp_wait0();
            __syncthreads();
            if(c<15){
                if(NP==3) stageB(sm+RBB+((c+1)&1)*24576,blobH+(c+1)*12288,blobL+(c+1)*12288,tid);
                else stageBh(sm+RBB+((c+1)&1)*24576,blobH+(c+1)*12288,tid);
                cp_commit();
            }
            u32 bb=smb+RBB+(c&1)*24576;
            u32 bh[4][4], bl[4][4];
#pragma unroll
            for(int j=0;j<4;j++){
                u32 ba=bb+boff+j*768;
                ldm4(bh[j],ba);
                if(NP==3) ldm4(bl[j],ba+12288);
            }
            u32 au=(u32)(((2*c+(g2>>1))^row)<<4);
            u32 ah[2][4], al[2][4];
            ldm4(ah[0],smb+RBH+arow+au);
            ldm4(ah[1],smb+RBH+arow+8192u+au);
            if(NP==3){
                ldm4(al[0],smb+RBL+arow+au);
                ldm4(al[1],smb+RBL+arow+8192u+au);
            }
#pragma unroll
            for(int mt=0;mt<2;mt++){
#pragma unroll
                for(int p=0;p<NP;p++){
                    const u32* A=(p==2)?al[mt]:ah[mt];
#pragma unroll
                    for(int nt=0;nt<8;nt++){
                        const u32* B=(p==1)?bl[nt>>1]:bh[nt>>1];
                        mma16816(acc[mt][nt],A,B[(nt&1)*2],B[(nt&1)*2+1]);
                    }
                }
            }
        }
        __syncthreads();
        if(L==0){
#pragma unroll
            for(int mt=0;mt<2;mt++){
                int r0=m0+mt*16+(lane>>2), r1=r0+8;
#pragma unroll
                for(int nt=0;nt<8;nt++){
                    int n=n0+nt*8+(lane&3)*2;
                    float v0=softplusf(acc[mt][nt][0]+bias[n]);
                    float v1=softplusf(acc[mt][nt][1]+bias[n+1]);
                    float v2=softplusf(acc[mt][nt][2]+bias[n]);
                    float v3=softplusf(acc[mt][nt][3]+bias[n+1]);
                    int o0=r0*512+(((n>>3)^(r0&7))<<4)+(n&7)*2;
                    int o1=r1*512+(((n>>3)^(r1&7))<<4)+(n&7)*2;
                    if(NP==3){
                        u32 h0,l0,h1,l1;
                        splitpk(v0,v1,h0,l0);
                        splitpk(v2,v3,h1,l1);
                        *(u32*)(sm+RBH+o0)=h0; *(u32*)(sm+RBL+o0)=l0;
                        *(u32*)(sm+RBH+o1)=h1; *(u32*)(sm+RBL+o1)=l1;
                    } else {
                        *(u32*)(sm+RBH+o0)=pkbf(v0,v1);
                        *(u32*)(sm+RBH+o1)=pkbf(v2,v3);
                    }
                }
            }
        } else {
#pragma unroll
            for(int mt=0;mt<2;mt++){
                float s0=0.f,s1=0.f;
#pragma unroll
                for(int nt=0;nt<8;nt++){
                    int n=n0+nt*8+(lane&3)*2;
                    s0+=softplusf(acc[mt][nt][0]+bias[n])*s_w4[n]
                       +softplusf(acc[mt][nt][1]+bias[n+1])*s_w4[n+1];
                    s1+=softplusf(acc[mt][nt][2]+bias[n])*s_w4[n]
                       +softplusf(acc[mt][nt][3]+bias[n+1])*s_w4[n+1];
                }
                s0+=__shfl_xor_sync(0xffffffffu,s0,1); s0+=__shfl_xor_sync(0xffffffffu,s0,2);
                s1+=__shfl_xor_sync(0xffffffffu,s1,1); s1+=__shfl_xor_sync(0xffffffffu,s1,2);
                if((lane&3)==0){
                    int r0=m0+mt*16+(lane>>2);
                    s_red[r0*4+nw]=s0;
                    s_red[(r0+8)*4+nw]=s1;
                }
            }
            __syncthreads();
            if(tid<64) s_f[tid]=s_red[tid*4]+s_red[tid*4+1]+s_red[tid*4+2]+s_red[tid*4+3]+b4v;
        }
        __syncthreads();
    }
}

__global__ void __launch_bounds__(256,1)
k_refine(const float* __restrict__ ray0,const float* __restrict__ rdir,
         const float* __restrict__ W1,const float* __restrict__ b1,
         const float* __restrict__ b2,const float* __restrict__ b3,
         const float* __restrict__ W4,const float* __restrict__ b4,
         float* __restrict__ out){
    extern __shared__ char sm[];
    __shared__ float s_bias2[256],s_bias3[256],s_w4[256],s_red[256];
    __shared__ float s_o[192],s_rd[192];
    __shared__ float s_dl[64],s_fl[64],s_dh[64],s_fh[64],s_dp[64],s_f[64],s_f0[64],s_fm[64];
    __shared__ float s_a[64],s_b[64];
    __shared__ int s_mask[64];
    int tid=threadIdx.x, rbase=blockIdx.x*64;
    u32 smb=smem_u32(sm);
    s_bias2[tid]=b2[tid]; s_bias3[tid]=b3[tid]; s_w4[tid]=W4[tid];
    float b4v=b4[0];
    if(tid<64){
        int r=rbase+tid;
        s_o[tid]=ray0[3*r]; s_o[64+tid]=ray0[3*r+1]; s_o[128+tid]=ray0[3*r+2];
        s_rd[tid]=rdir[3*r]; s_rd[64+tid]=rdir[3*r+1]; s_rd[128+tid]=rdir[3*r+2];
        s_a[tid]=g_a[r]; s_b[tid]=g_b[r];
    }
    float* vbuf=(float*)sm;
    for(int i=tid;i<64*SSAMP;i+=256) vbuf[i]=g_val[rbase*SSAMP+i];
    __syncthreads();
    if(tid<64){
        const float* v=vbuf+tid*SSAMP;
        float best=1e30f; int bidx=0;
        for(int s=0;s<SSAMP;s++){
            float c;
            if(s<SSAMP-1){ float pr=v[s]*v[s+1];
                float sg=(pr>0.f)?1.f:((pr<0.f)?-1.f:0.f); c=sg*(float)(SSAMP-s); }
            else c=1.f;
            if(c<best){ best=c; bidx=s; }
        }
        float fl=v[bidx];
        int ihi=bidx+1; if(ihi>SSAMP-1) ihi=SSAMP-1;
        float dl=s_a[tid]+(float)bidx*s_b[tid];
        float dh=s_a[tid]+(float)ihi*s_b[tid];
        float fh=v[ihi];
        s_mask[tid]=(best<0.f)&&(fl<0.f)&&(v[0]<0.f);
        s_dl[tid]=dl; s_fl[tid]=fl; s_dh[tid]=dh; s_fh[tid]=fh;
        s_dp[tid]=secantf(dl,fl,dh,fh);
    }
    __syncthreads();
    for(int it=0;it<8;it++){
        eval_mma<1>(sm,smb,tid,0.f,W1,b1,s_o,s_rd,s_dp,s_bias2,s_bias3,s_w4,b4v,s_red,s_f);
        if(tid<64){
            float fm=s_f[tid];
            float dl=s_dl[tid],fl=s_fl[tid],dh=s_dh[tid],fh=s_fh[tid],dp=s_dp[tid];
            if(fm<0.f){ dl=dp; fl=fm; } else { dh=dp; fh=fm; }
            s_dl[tid]=dl; s_fl[tid]=fl; s_dh[tid]=dh; s_fh[tid]=fh;
            s_dp[tid]=secantf(dl,fl,dh,fh);
        }
        __syncthreads();
    }
    eval_mma<3>(sm,smb,tid,0.f,W1,b1,s_o,s_rd,s_dp,s_bias2,s_bias3,s_w4,b4v,s_red,s_f);
    if(tid<64) s_f0[tid]=s_f[tid];
    __syncthreads();
    eval_mma<3>(sm,smb,tid,-FDE,W1,b1,s_o,s_rd,s_dp,s_bias2,s_bias3,s_w4,b4v,s_red,s_f);
    if(tid<64) s_fm[tid]=s_f[tid];
    __syncthreads();
    eval_mma<3>(sm,smb,tid,FDE,W1,b1,s_o,s_rd,s_dp,s_bias2,s_bias3,s_w4,b4v,s_red,s_f);
    if(tid<64){
        float df=(s_f[tid]-s_fm[tid])*(0.5f/FDE);
        if(fabsf(df)<1e-6f) df=(df<0.f)?-1e-6f:1e-6f;
        float dout=s_dp[tid]-s_f0[tid]/df;
        out[rbase+tid]=s_mask[tid]?dout:0.f;
    }
}

extern "C" void kernel_launch(void* const* d_in,const int* in_sizes,int n_in,
                              void* d_out,int out_size){
    const float* ray0=(const float*)d_in[0];
    const float* rdir=(const float*)d_in[1];
    const float* W1=(const float*)d_in[2];
    const float* b1=(const float*)d_in[3];
    const float* W2=(const float*)d_in[4];
    const float* b2=(const float*)d_in[5];
    const float* W3=(const float*)d_in[6];
    const float* b3=(const float*)d_in[7];
    const float* W4=(const float*)d_in[8];
    const float* b4=(const float*)d_in[9];
    float* out=(float*)d_out;
    const int smemBig=90112;
    const int smemRef=114688;
    cudaFuncSetAttribute(k_big,cudaFuncAttributeMaxDynamicSharedMemorySize,smemBig);
    cudaFuncSetAttribute(k_refine,cudaFuncAttributeMaxDynamicSharedMemorySize,smemRef);
    k_prep<<<512,256>>>(W2,W3);
    k_setup<<<(NRAYS+255)/256,256>>>(ray0,rdir);
    k_big<<<NRAYS,256,smemBig>>>(ray0,rdir,W1,b1,b2,b3,W4,b4);
    k_refine<<<NRAYS/64,256,smemRef>>>(ray0,rdir,W1,b1,b2,b3,W4,b4,out);
}

// round 15
// speedup vs baseline: 4.3248x; 1.0307x over previous
#include <cuda_runtime.h>
#include <cuda_bf16.h>
#include <cstdint>
typedef unsigned long long u64;
typedef unsigned int u32;

#define NRAYS 8192
#define SSAMP 128
#define P_DIST 0.55f
#define CUBE_EPS 1e-6f
#define FDE 2e-3f

__device__ float g_val[NRAYS * SSAMP];
__device__ float g_a[NRAYS];
__device__ float g_b[NRAYS];
// [layer][hi/lo]: 16 chunks x (256 n-rows x 48B pitch, 16 k bf16) = 196608 B
__device__ __align__(128) unsigned char g_WB[2][2][196608];

// ---- helpers ----
__device__ __forceinline__ u32 smem_u32(const void* p){ return (u32)__cvta_generic_to_shared(p); }
__device__ __forceinline__ float softplusf(float x){
    return fmaxf(x,0.f)+__logf(1.f+__expf(-fabsf(x)));
}
__device__ __forceinline__ float secantf(float dl,float fl,float dh,float fh){
    float den=fh-fl; if(fabsf(den)<1e-12f) den=1e-12f; return -fl*(dh-dl)/den+dl; }
__device__ __forceinline__ void cp16(u32 dst,const void* src){ asm volatile("cp.async.cg.shared.global [%0],[%1],16;"::"r"(dst),"l"(src):"memory"); }
__device__ __forceinline__ void cp_commit(){ asm volatile("cp.async.commit_group;":::"memory"); }
__device__ __forceinline__ void cp_wait0(){ asm volatile("cp.async.wait_group 0;":::"memory"); }
__device__ __forceinline__ void cp_wait1(){ asm volatile("cp.async.wait_group 1;":::"memory"); }

__device__ __forceinline__ void ldm4(u32* r,u32 a){
    asm volatile("ldmatrix.sync.aligned.m8n8.x4.shared.b16 {%0,%1,%2,%3},[%4];"
        :"=r"(r[0]),"=r"(r[1]),"=r"(r[2]),"=r"(r[3]):"r"(a)); }
__device__ __forceinline__ void mma16816(float* d,const u32* a,u32 b0,u32 b1){
    asm volatile("mma.sync.aligned.m16n8k16.row.col.f32.bf16.bf16.f32 "
        "{%0,%1,%2,%3},{%4,%5,%6,%7},{%8,%9},{%0,%1,%2,%3};"
        :"+f"(d[0]),"+f"(d[1]),"+f"(d[2]),"+f"(d[3])
        :"r"(a[0]),"r"(a[1]),"r"(a[2]),"r"(a[3]),"r"(b0),"r"(b1)); }
__device__ __forceinline__ void splitpk(float x,float y,u32&h,u32&l){
    __nv_bfloat16 hx=__float2bfloat16_rn(x), hy=__float2bfloat16_rn(y);
    __nv_bfloat16 lx=__float2bfloat16_rn(x-__bfloat162float(hx));
    __nv_bfloat16 ly=__float2bfloat16_rn(y-__bfloat162float(hy));
    h=((u32)*(unsigned short*)&hx)|(((u32)*(unsigned short*)&hy)<<16);
    l=((u32)*(unsigned short*)&lx)|(((u32)*(unsigned short*)&ly)<<16);
}
__device__ __forceinline__ u32 pkbf(float x,float y){
    __nv_bfloat16 hx=__float2bfloat16_rn(x), hy=__float2bfloat16_rn(y);
    return ((u32)*(unsigned short*)&hx)|(((u32)*(unsigned short*)&hy)<<16);
}

// ---- k_prep ----
__global__ void k_prep(const float* __restrict__ W2,const float* __restrict__ W3){
    int idx=blockIdx.x*blockDim.x+threadIdx.x;
    int layer=idx>>16, e=idx&65535;
    const float* W=layer?W3:W2;
    int k=e>>8, n=e&255;
    float w=W[e];
    __nv_bfloat16 hi=__float2bfloat16_rn(w);
    __nv_bfloat16 lo=__float2bfloat16_rn(w-__bfloat162float(hi));
    int c=k>>4, kk=k&15;
    size_t off=(size_t)c*12288+(size_t)n*48+(size_t)kk*2;
    *(__nv_bfloat16*)(g_WB[layer][0]+off)=hi;
    *(__nv_bfloat16*)(g_WB[layer][1]+off)=lo;
}

// ---- cube intersection ----
__global__ void k_setup(const float* __restrict__ ray0,const float* __restrict__ rdir){
    int r=blockIdx.x*blockDim.x+threadIdx.x; if(r>=NRAYS) return;
    float o0=ray0[3*r],o1=ray0[3*r+1],o2=ray0[3*r+2];
    float r0=rdir[3*r],r1=rdir[3*r+1],r2=rdir[3*r+2];
    float ov[3]={o0,o1,o2},rv[3]={r0,r1,r2},t2[2]={0.f,0.f};
    int cnt=0; float rn=sqrtf(r0*r0+r1*r1+r2*r2);
#pragma unroll
    for(int i=0;i<6;i++){
        int ax=i%3; float pv=(i<3)?P_DIST:-P_DIST;
        float den=rv[ax]; if(fabsf(den)<1e-9f) den=1e-9f;
        float t=(pv-ov[ax])/den;
        float q0=o0+t*r0,q1=o1+t*r1,q2=o2+t*r2;
        bool ins=(fabsf(q0)<=P_DIST+CUBE_EPS)&&(fabsf(q1)<=P_DIST+CUBE_EPS)&&(fabsf(q2)<=P_DIST+CUBE_EPS);
        if(ins){ if(cnt<2){ float e0=q0-o0,e1=q1-o1,e2=q2-o2;
                t2[cnt]=sqrtf(e0*e0+e1*e1+e2*e2)/rn; } cnt++; }
    }
    float a,b;
    if(cnt==2){ float lo=fminf(t2[0],t2[1]),hi=fmaxf(t2[0],t2[1]); a=lo; b=(hi-lo)*(1.f/127.f); }
    else { a=0.f; b=2.4f/127.f; }
    g_a[r]=a; g_b[r]=b;
}

// ---- staging ----
__device__ __forceinline__ void stageB(char* dst,const unsigned char* sH,const unsigned char* sL,int tid){
    u32 d=smem_u32(dst);
#pragma unroll
    for(int j=0;j<3;j++){ int u=tid+j*256; cp16(d+u*16,sH+u*16); }
#pragma unroll
    for(int j=0;j<3;j++){ int u=tid+j*256; cp16(d+12288+u*16,sL+u*16); }
}
__device__ __forceinline__ void stageBh(char* dst,const unsigned char* sH,int tid){
    u32 d=smem_u32(dst);
#pragma unroll
    for(int j=0;j<3;j++){ int u=tid+j*256; cp16(d+u*16,sH+u*16); }
}

// ---- k_big: one ray/CTA, M-split (2 passes of M=64), 2 CTAs/SM, 3-deep B pipe ----
// smem: A_hi 64KB @0, Bbuf 3x12288 @65536  (total 102400)
#define ABH 0
#define BBF 65536
__global__ void __launch_bounds__(256,2)
k_big(const float* __restrict__ ray0,const float* __restrict__ rdir,
      const float* __restrict__ W1,const float* __restrict__ b1,
      const float* __restrict__ b2,const float* __restrict__ b3,
      const float* __restrict__ W4,const float* __restrict__ b4){
    extern __shared__ char sm[];
    __shared__ float s_bias[256], s_w4[256], s_red[512], s_c[512];
    int tid=threadIdx.x, lane=tid&31, warp=tid>>5, ray=blockIdx.x;
    u32 smb=smem_u32(sm);

    // prefetch first two B chunks of layer-2 before layer-1 compute
    stageBh(sm+BBF,g_WB[0][0],tid); cp_commit();
    stageBh(sm+BBF+12288,g_WB[0][0]+12288,tid); cp_commit();

    float a=g_a[ray], st=g_b[ray];
    float ox=ray0[ray*3],oy=ray0[ray*3+1],oz=ray0[ray*3+2];
    float dx=rdir[ray*3],dy=rdir[ray*3+1],dz=rdir[ray*3+2];
    s_c[2*tid]  =fmaf(ox,W1[tid],fmaf(oy,W1[256+tid],fmaf(oz,W1[512+tid],b1[tid])));
    s_c[2*tid+1]=fmaf(dx,W1[tid],fmaf(dy,W1[256+tid],dz*W1[512+tid]));
    __syncthreads();
    {
        int m=tid&127, kh=tid>>7;
        float d=a+(float)m*st;
#pragma unroll 4
        for(int j=0;j<128;j+=2){
            int k=kh*128+j;
            float2 ca=*(float2*)(s_c+2*k);
            float2 cb=*(float2*)(s_c+2*k+2);
            float v0=softplusf(fmaf(d,ca.y,ca.x));
            float v1=softplusf(fmaf(d,cb.y,cb.x));
            int off=m*512+((((k>>3))^(m&7))<<4)+((k&7)<<1);
            *(u32*)(sm+ABH+off)=pkbf(v0,v1);
        }
    }

    int g2=lane>>3, row=lane&7;
    int mw=warp&1, nw=warp>>1;
    int n0=nw*64;
    u32 boff=(u32)((n0+(g2>>1)*8+row)*48+(g2&1)*16);

    for(int L=0;L<2;L++){
        __syncthreads();
        s_bias[tid]=L?b3[tid]:b2[tid];
        if(L) s_w4[tid]=W4[tid];
        const unsigned char* blobH=g_WB[L][0];
        for(int mh=0;mh<2;mh++){
            int m0=mh*64+mw*32;
            u32 arow=(u32)((m0+(g2&1)*8+row)*512);
            float acc[2][8][4];
#pragma unroll
            for(int i=0;i<2;i++)
#pragma unroll
                for(int j=0;j<8;j++){ acc[i][j][0]=0.f; acc[i][j][1]=0.f; acc[i][j][2]=0.f; acc[i][j][3]=0.f; }
            if(!(L==0&&mh==0)){
                stageBh(sm+BBF,blobH,tid); cp_commit();
                stageBh(sm+BBF+12288,blobH+12288,tid); cp_commit();
            }
            for(int c=0;c<16;c++){
                if(c<14) cp_wait1(); else cp_wait0();
                __syncthreads();
                if(c<14){ stageBh(sm+BBF+((c+2)%3)*12288,blobH+(c+2)*12288,tid); cp_commit(); }
                u32 bb=smb+BBF+(c%3)*12288;
                u32 bh[4][4];
#pragma unroll
                for(int j=0;j<4;j++) ldm4(bh[j],bb+boff+j*768);
                u32 au=(u32)(((2*c+(g2>>1))^row)<<4);
                u32 ah[2][4];
                ldm4(ah[0],smb+ABH+arow+au);
                ldm4(ah[1],smb+ABH+arow+8192u+au);
#pragma unroll
                for(int mt=0;mt<2;mt++)
#pragma unroll
                    for(int nt=0;nt<8;nt++){
                        const u32* B=bh[nt>>1];
                        mma16816(acc[mt][nt],ah[mt],B[(nt&1)*2],B[(nt&1)*2+1]);
                    }
            }
            __syncthreads();
            if(L==0){
#pragma unroll
                for(int mt=0;mt<2;mt++){
                    int r0=m0+mt*16+(lane>>2), r1=r0+8;
#pragma unroll
                    for(int nt=0;nt<8;nt++){
                        int n=n0+nt*8+(lane&3)*2;
                        float v0=softplusf(acc[mt][nt][0]+s_bias[n]);
                        float v1=softplusf(acc[mt][nt][1]+s_bias[n+1]);
                        float v2=softplusf(acc[mt][nt][2]+s_bias[n]);
                        float v3=softplusf(acc[mt][nt][3]+s_bias[n+1]);
                        int o0=r0*512+(((n>>3)^(r0&7))<<4)+(n&7)*2;
                        int o1=r1*512+(((n>>3)^(r1&7))<<4)+(n&7)*2;
                        *(u32*)(sm+ABH+o0)=pkbf(v0,v1);
                        *(u32*)(sm+ABH+o1)=pkbf(v2,v3);
                    }
                }
            } else {
#pragma unroll
                for(int mt=0;mt<2;mt++){
                    float s0=0.f,s1=0.f;
#pragma unroll
                    for(int nt=0;nt<8;nt++){
                        int n=n0+nt*8+(lane&3)*2;
                        s0+=softplusf(acc[mt][nt][0]+s_bias[n])*s_w4[n]
                           +softplusf(acc[mt][nt][1]+s_bias[n+1])*s_w4[n+1];
                        s1+=softplusf(acc[mt][nt][2]+s_bias[n])*s_w4[n]
                           +softplusf(acc[mt][nt][3]+s_bias[n+1])*s_w4[n+1];
                    }
                    s0+=__shfl_xor_sync(0xffffffffu,s0,1); s0+=__shfl_xor_sync(0xffffffffu,s0,2);
                    s1+=__shfl_xor_sync(0xffffffffu,s1,1); s1+=__shfl_xor_sync(0xffffffffu,s1,2);
                    if((lane&3)==0){
                        int r0=m0+mt*16+(lane>>2);
                        s_red[r0*4+nw]=s0;
                        s_red[(r0+8)*4+nw]=s1;
                    }
                }
            }
        }
    }
    __syncthreads();
    if(tid<128)
        g_val[ray*SSAMP+tid]=s_red[tid*4]+s_red[tid*4+1]+s_red[tid*4+2]+s_red[tid*4+3]+b4[0];
}

// ======== k_refine: HMMA evals, M=64; NP=1 secant, NP=3 for all finals ========
#define RBH 0
#define RBL 32768
#define RBB 65536   // 2 x 24576
template<int NP>
__device__ __forceinline__ void eval_mma(char* sm,u32 smb,int tid,float delta,
    const float* __restrict__ W1,const float* __restrict__ b1,
    const float* s_o,const float* s_rd,const float* s_dp,
    const float* s_bias2,const float* s_bias3,const float* s_w4,float b4v,
    float* s_red,float* s_f){
    int lane=tid&31, warp=tid>>5;
    {
        int m=tid&63, kg=tid>>6;
        float d=s_dp[m]+delta;
        float px=s_o[m]+d*s_rd[m], py=s_o[64+m]+d*s_rd[64+m], pz=s_o[128+m]+d*s_rd[128+m];
#pragma unroll 4
        for(int j=0;j<64;j+=2){
            int k=kg*64+j;
            float z0=fmaf(px,W1[k],fmaf(py,W1[256+k],fmaf(pz,W1[512+k],b1[k])));
            float z1=fmaf(px,W1[k+1],fmaf(py,W1[257+k],fmaf(pz,W1[513+k],b1[k+1])));
            float v0=softplusf(z0), v1=softplusf(z1);
            int off=m*512+((((k>>3))^(m&7))<<4)+((k&7)<<1);
            if(NP==3){
                u32 h,l; splitpk(v0,v1,h,l);
                *(u32*)(sm+RBH+off)=h;
                *(u32*)(sm+RBL+off)=l;
            } else {
                *(u32*)(sm+RBH+off)=pkbf(v0,v1);
            }
        }
    }
    int g2=lane>>3, row=lane&7;
    int mw=warp&1, nw=warp>>1;
    int m0=mw*32, n0=nw*64;
    u32 arow=(u32)((m0+(g2&1)*8+row)*512);
    u32 boff=(u32)((n0+(g2>>1)*8+row)*48+(g2&1)*16);

    for(int L=0;L<2;L++){
        const float* bias=L?s_bias3:s_bias2;
        const unsigned char* blobH=g_WB[L][0];
        const unsigned char* blobL=g_WB[L][1];
        float acc[2][8][4];
#pragma unroll
        for(int i=0;i<2;i++)
#pragma unroll
            for(int j=0;j<8;j++){ acc[i][j][0]=0.f; acc[i][j][1]=0.f; acc[i][j][2]=0.f; acc[i][j][3]=0.f; }
        if(NP==3) stageB(sm+RBB,blobH,blobL,tid); else stageBh(sm+RBB,blobH,tid);
        cp_commit();
        for(int c=0;c<16;c++){
            cp_wait0();
            __syncthreads();
            if(c<15){
                if(NP==3) stageB(sm+RBB+((c+1)&1)*24576,blobH+(c+1)*12288,blobL+(c+1)*12288,tid);
                else stageBh(sm+RBB+((c+1)&1)*24576,blobH+(c+1)*12288,tid);
                cp_commit();
            }
            u32 bb=smb+RBB+(c&1)*24576;
            u32 bh[4][4], bl[4][4];
#pragma unroll
            for(int j=0;j<4;j++){
                u32 ba=bb+boff+j*768;
                ldm4(bh[j],ba);
                if(NP==3) ldm4(bl[j],ba+12288);
            }
            u32 au=(u32)(((2*c+(g2>>1))^row)<<4);
            u32 ah[2][4], al[2][4];
            ldm4(ah[0],smb+RBH+arow+au);
            ldm4(ah[1],smb+RBH+arow+8192u+au);
            if(NP==3){
                ldm4(al[0],smb+RBL+arow+au);
                ldm4(al[1],smb+RBL+arow+8192u+au);
            }
#pragma unroll
            for(int mt=0;mt<2;mt++){
#pragma unroll
                for(int p=0;p<NP;p++){
                    const u32* A=(p==2)?al[mt]:ah[mt];
#pragma unroll
                    for(int nt=0;nt<8;nt++){
                        const u32* B=(p==1)?bl[nt>>1]:bh[nt>>1];
                        mma16816(acc[mt][nt],A,B[(nt&1)*2],B[(nt&1)*2+1]);
                    }
                }
            }
        }
        __syncthreads();
        if(L==0){
#pragma unroll
            for(int mt=0;mt<2;mt++){
                int r0=m0+mt*16+(lane>>2), r1=r0+8;
#pragma unroll
                for(int nt=0;nt<8;nt++){
                    int n=n0+nt*8+(lane&3)*2;
                    float v0=softplusf(acc[mt][nt][0]+bias[n]);
                    float v1=softplusf(acc[mt][nt][1]+bias[n+1]);
                    float v2=softplusf(acc[mt][nt][2]+bias[n]);
                    float v3=softplusf(acc[mt][nt][3]+bias[n+1]);
                    int o0=r0*512+(((n>>3)^(r0&7))<<4)+(n&7)*2;
                    int o1=r1*512+(((n>>3)^(r1&7))<<4)+(n&7)*2;
                    if(NP==3){
                        u32 h0,l0,h1,l1;
                        splitpk(v0,v1,h0,l0);
                        splitpk(v2,v3,h1,l1);
                        *(u32*)(sm+RBH+o0)=h0; *(u32*)(sm+RBL+o0)=l0;
                        *(u32*)(sm+RBH+o1)=h1; *(u32*)(sm+RBL+o1)=l1;
                    } else {
                        *(u32*)(sm+RBH+o0)=pkbf(v0,v1);
                        *(u32*)(sm+RBH+o1)=pkbf(v2,v3);
                    }
                }
            }
        } else {
#pragma unroll
            for(int mt=0;mt<2;mt++){
                float s0=0.f,s1=0.f;
#pragma unroll
                for(int nt=0;nt<8;nt++){
                    int n=n0+nt*8+(lane&3)*2;
                    s0+=softplusf(acc[mt][nt][0]+bias[n])*s_w4[n]
                       +softplusf(acc[mt][nt][1]+bias[n+1])*s_w4[n+1];
                    s1+=softplusf(acc[mt][nt][2]+bias[n])*s_w4[n]
                       +softplusf(acc[mt][nt][3]+bias[n+1])*s_w4[n+1];
                }
                s0+=__shfl_xor_sync(0xffffffffu,s0,1); s0+=__shfl_xor_sync(0xffffffffu,s0,2);
                s1+=__shfl_xor_sync(0xffffffffu,s1,1); s1+=__shfl_xor_sync(0xffffffffu,s1,2);
                if((lane&3)==0){
                    int r0=m0+mt*16+(lane>>2);
                    s_red[r0*4+nw]=s0;
                    s_red[(r0+8)*4+nw]=s1;
                }
            }
            __syncthreads();
            if(tid<64) s_f[tid]=s_red[tid*4]+s_red[tid*4+1]+s_red[tid*4+2]+s_red[tid*4+3]+b4v;
        }
        __syncthreads();
    }
}

__global__ void __launch_bounds__(256,1)
k_refine(const float* __restrict__ ray0,const float* __restrict__ rdir,
         const float* __restrict__ W1,const float* __restrict__ b1,
         const float* __restrict__ b2,const float* __restrict__ b3,
         const float* __restrict__ W4,const float* __restrict__ b4,
         float* __restrict__ out){
    extern __shared__ char sm[];
    __shared__ float s_bias2[256],s_bias3[256],s_w4[256],s_red[256];
    __shared__ float s_o[192],s_rd[192];
    __shared__ float s_dl[64],s_fl[64],s_dh[64],s_fh[64],s_dp[64],s_f[64],s_f0[64],s_fm[64];
    __shared__ float s_a[64],s_b[64];
    __shared__ int s_mask[64];
    int tid=threadIdx.x, rbase=blockIdx.x*64;
    u32 smb=smem_u32(sm);
    s_bias2[tid]=b2[tid]; s_bias3[tid]=b3[tid]; s_w4[tid]=W4[tid];
    float b4v=b4[0];
    if(tid<64){
        int r=rbase+tid;
        s_o[tid]=ray0[3*r]; s_o[64+tid]=ray0[3*r+1]; s_o[128+tid]=ray0[3*r+2];
        s_rd[tid]=rdir[3*r]; s_rd[64+tid]=rdir[3*r+1]; s_rd[128+tid]=rdir[3*r+2];
        s_a[tid]=g_a[r]; s_b[tid]=g_b[r];
    }
    float* vbuf=(float*)sm;
    for(int i=tid;i<64*SSAMP;i+=256) vbuf[i]=g_val[rbase*SSAMP+i];
    __syncthreads();
    if(tid<64){
        const float* v=vbuf+tid*SSAMP;
        float best=1e30f; int bidx=0;
        for(int s=0;s<SSAMP;s++){
            float c;
            if(s<SSAMP-1){ float pr=v[s]*v[s+1];
                float sg=(pr>0.f)?1.f:((pr<0.f)?-1.f:0.f); c=sg*(float)(SSAMP-s); }
            else c=1.f;
            if(c<best){ best=c; bidx=s; }
        }
        float fl=v[bidx];
        int ihi=bidx+1; if(ihi>SSAMP-1) ihi=SSAMP-1;
        float dl=s_a[tid]+(float)bidx*s_b[tid];
        float dh=s_a[tid]+(float)ihi*s_b[tid];
        float fh=v[ihi];
        s_mask[tid]=(best<0.f)&&(fl<0.f)&&(v[0]<0.f);
        s_dl[tid]=dl; s_fl[tid]=fl; s_dh[tid]=dh; s_fh[tid]=fh;
        s_dp[tid]=secantf(dl,fl,dh,fh);
    }
    __syncthreads();
    for(int it=0;it<8;it++){
        eval_mma<1>(sm,smb,tid,0.f,W1,b1,s_o,s_rd,s_dp,s_bias2,s_bias3,s_w4,b4v,s_red,s_f);
        if(tid<64){
            float fm=s_f[tid];
            float dl=s_dl[tid],fl=s_fl[tid],dh=s_dh[tid],fh=s_fh[tid],dp=s_dp[tid];
            if(fm<0.f){ dl=dp; fl=fm; } else { dh=dp; fh=fm; }
            s_dl[tid]=dl; s_fl[tid]=fl; s_dh[tid]=dh; s_fh[tid]=fh;
            s_dp[tid]=secantf(dl,fl,dh,fh);
        }
        __syncthreads();
    }
    eval_mma<3>(sm,smb,tid,0.f,W1,b1,s_o,s_rd,s_dp,s_bias2,s_bias3,s_w4,b4v,s_red,s_f);
    if(tid<64) s_f0[tid]=s_f[tid];
    __syncthreads();
    eval_mma<3>(sm,smb,tid,-FDE,W1,b1,s_o,s_rd,s_dp,s_bias2,s_bias3,s_w4,b4v,s_red,s_f);
    if(tid<64) s_fm[tid]=s_f[tid];
    __syncthreads();
    eval_mma<3>(sm,smb,tid,FDE,W1,b1,s_o,s_rd,s_dp,s_bias2,s_bias3,s_w4,b4v,s_red,s_f);
    if(tid<64){
        float df=(s_f[tid]-s_fm[tid])*(0.5f/FDE);
        if(fabsf(df)<1e-6f) df=(df<0.f)?-1e-6f:1e-6f;
        float dout=s_dp[tid]-s_f0[tid]/df;
        out[rbase+tid]=s_mask[tid]?dout:0.f;
    }
}

extern "C" void kernel_launch(void* const* d_in,const int* in_sizes,int n_in,
                              void* d_out,int out_size){
    const float* ray0=(const float*)d_in[0];
    const float* rdir=(const float*)d_in[1];
    const float* W1=(const float*)d_in[2];
    const float* b1=(const float*)d_in[3];
    const float* W2=(const float*)d_in[4];
    const float* b2=(const float*)d_in[5];
    const float* W3=(const float*)d_in[6];
    const float* b3=(const float*)d_in[7];
    const float* W4=(const float*)d_in[8];
    const float* b4=(const float*)d_in[9];
    float* out=(float*)d_out;
    const int smemBig=102400;
    const int smemRef=114688;
    cudaFuncSetAttribute(k_big,cudaFuncAttributeMaxDynamicSharedMemorySize,smemBig);
    cudaFuncSetAttribute(k_refine,cudaFuncAttributeMaxDynamicSharedMemorySize,smemRef);
    k_prep<<<512,256>>>(W2,W3);
    k_setup<<<(NRAYS+255)/256,256>>>(ray0,rdir);
    k_big<<<NRAYS,256,smemBig>>>(ray0,rdir,W1,b1,b2,b3,W4,b4);
    k_refine<<<NRAYS/64,256,smemRef>>>(ray0,rdir,W1,b1,b2,b3,W4,b4,out);
}

// round 16
// speedup vs baseline: 4.7309x; 1.0939x over previous
#include <cuda_runtime.h>
#include <cuda_bf16.h>
#include <cstdint>
typedef unsigned long long u64;
typedef unsigned int u32;

#define NRAYS 8192
#define SSAMP 128
#define P_DIST 0.55f
#define CUBE_EPS 1e-6f
#define FDE 2e-3f

__device__ float g_val[NRAYS * SSAMP];
__device__ float g_a[NRAYS];
__device__ float g_b[NRAYS];
// [layer][hi/lo]: 16 chunks x (256 n-rows x 48B pitch, 16 k bf16) = 196608 B
__device__ __align__(128) unsigned char g_WB[2][2][196608];

// ---- helpers ----
__device__ __forceinline__ u32 smem_u32(const void* p){ return (u32)__cvta_generic_to_shared(p); }
__device__ __forceinline__ float softplusf(float x){
    return fmaxf(x,0.f)+__logf(1.f+__expf(-fabsf(x)));
}
__device__ __forceinline__ float secantf(float dl,float fl,float dh,float fh){
    float den=fh-fl; if(fabsf(den)<1e-12f) den=1e-12f; return -fl*(dh-dl)/den+dl; }
__device__ __forceinline__ void cp16(u32 dst,const void* src){ asm volatile("cp.async.cg.shared.global [%0],[%1],16;"::"r"(dst),"l"(src):"memory"); }
__device__ __forceinline__ void cp_commit(){ asm volatile("cp.async.commit_group;":::"memory"); }
__device__ __forceinline__ void cp_wait0(){ asm volatile("cp.async.wait_group 0;":::"memory"); }
__device__ __forceinline__ void cp_wait1(){ asm volatile("cp.async.wait_group 1;":::"memory"); }

__device__ __forceinline__ void ldm4(u32* r,u32 a){
    asm volatile("ldmatrix.sync.aligned.m8n8.x4.shared.b16 {%0,%1,%2,%3},[%4];"
        :"=r"(r[0]),"=r"(r[1]),"=r"(r[2]),"=r"(r[3]):"r"(a)); }
__device__ __forceinline__ void mma16816(float* d,const u32* a,u32 b0,u32 b1){
    asm volatile("mma.sync.aligned.m16n8k16.row.col.f32.bf16.bf16.f32 "
        "{%0,%1,%2,%3},{%4,%5,%6,%7},{%8,%9},{%0,%1,%2,%3};"
        :"+f"(d[0]),"+f"(d[1]),"+f"(d[2]),"+f"(d[3])
        :"r"(a[0]),"r"(a[1]),"r"(a[2]),"r"(a[3]),"r"(b0),"r"(b1)); }
// packed bf16x2 convert: low=x, high=y (round-to-nearest, same as __float2bfloat16_rn)
__device__ __forceinline__ u32 pkbf(float x,float y){
    u32 r; asm("cvt.rn.satfinite.bf16x2.f32 %0,%1,%2;":"=r"(r):"f"(y),"f"(x)); return r;
}
__device__ __forceinline__ void splitpk(float x,float y,u32&h,u32&l){
    h=pkbf(x,y);
    float rx=x-__uint_as_float(h<<16);
    float ry=y-__uint_as_float(h&0xffff0000u);
    l=pkbf(rx,ry);
}

// ---- k_prep ----
__global__ void k_prep(const float* __restrict__ W2,const float* __restrict__ W3){
    int idx=blockIdx.x*blockDim.x+threadIdx.x;
    int layer=idx>>16, e=idx&65535;
    const float* W=layer?W3:W2;
    int k=e>>8, n=e&255;
    float w=W[e];
    __nv_bfloat16 hi=__float2bfloat16_rn(w);
    __nv_bfloat16 lo=__float2bfloat16_rn(w-__bfloat162float(hi));
    int c=k>>4, kk=k&15;
    size_t off=(size_t)c*12288+(size_t)n*48+(size_t)kk*2;
    *(__nv_bfloat16*)(g_WB[layer][0]+off)=hi;
    *(__nv_bfloat16*)(g_WB[layer][1]+off)=lo;
}

// ---- cube intersection ----
__global__ void k_setup(const float* __restrict__ ray0,const float* __restrict__ rdir){
    int r=blockIdx.x*blockDim.x+threadIdx.x; if(r>=NRAYS) return;
    float o0=ray0[3*r],o1=ray0[3*r+1],o2=ray0[3*r+2];
    float r0=rdir[3*r],r1=rdir[3*r+1],r2=rdir[3*r+2];
    float ov[3]={o0,o1,o2},rv[3]={r0,r1,r2},t2[2]={0.f,0.f};
    int cnt=0; float rn=sqrtf(r0*r0+r1*r1+r2*r2);
#pragma unroll
    for(int i=0;i<6;i++){
        int ax=i%3; float pv=(i<3)?P_DIST:-P_DIST;
        float den=rv[ax]; if(fabsf(den)<1e-9f) den=1e-9f;
        float t=(pv-ov[ax])/den;
        float q0=o0+t*r0,q1=o1+t*r1,q2=o2+t*r2;
        bool ins=(fabsf(q0)<=P_DIST+CUBE_EPS)&&(fabsf(q1)<=P_DIST+CUBE_EPS)&&(fabsf(q2)<=P_DIST+CUBE_EPS);
        if(ins){ if(cnt<2){ float e0=q0-o0,e1=q1-o1,e2=q2-o2;
                t2[cnt]=sqrtf(e0*e0+e1*e1+e2*e2)/rn; } cnt++; }
    }
    float a,b;
    if(cnt==2){ float lo=fminf(t2[0],t2[1]),hi=fmaxf(t2[0],t2[1]); a=lo; b=(hi-lo)*(1.f/127.f); }
    else { a=0.f; b=2.4f/127.f; }
    g_a[r]=a; g_b[r]=b;
}

// ---- staging ----
__device__ __forceinline__ void stageB(char* dst,const unsigned char* sH,const unsigned char* sL,int tid){
    u32 d=smem_u32(dst);
#pragma unroll
    for(int j=0;j<3;j++){ int u=tid+j*256; cp16(d+u*16,sH+u*16); }
#pragma unroll
    for(int j=0;j<3;j++){ int u=tid+j*256; cp16(d+12288+u*16,sL+u*16); }
}
__device__ __forceinline__ void stageBh(char* dst,const unsigned char* sH,int tid){
    u32 d=smem_u32(dst);
#pragma unroll
    for(int j=0;j<3;j++){ int u=tid+j*256; cp16(d+u*16,sH+u*16); }
}

// ---- k_big: one ray/CTA, M-split (2 passes of M=64), 2 CTAs/SM, 3-deep B pipe ----
// smem: A_hi 64KB @0, Bbuf 3x12288 @65536  (total 102400)
#define ABH 0
#define BBF 65536
__global__ void __launch_bounds__(256,2)
k_big(const float* __restrict__ ray0,const float* __restrict__ rdir,
      const float* __restrict__ W1,const float* __restrict__ b1,
      const float* __restrict__ b2,const float* __restrict__ b3,
      const float* __restrict__ W4,const float* __restrict__ b4){
    extern __shared__ char sm[];
    __shared__ float s_bias[256], s_w4[256], s_red[512], s_c[512];
    int tid=threadIdx.x, lane=tid&31, warp=tid>>5, ray=blockIdx.x;
    u32 smb=smem_u32(sm);

    // prefetch first two B chunks of layer-2 before layer-1 compute
    stageBh(sm+BBF,g_WB[0][0],tid); cp_commit();
    stageBh(sm+BBF+12288,g_WB[0][0]+12288,tid); cp_commit();

    float a=g_a[ray], st=g_b[ray];
    float ox=ray0[ray*3],oy=ray0[ray*3+1],oz=ray0[ray*3+2];
    float dx=rdir[ray*3],dy=rdir[ray*3+1],dz=rdir[ray*3+2];
    s_c[2*tid]  =fmaf(ox,W1[tid],fmaf(oy,W1[256+tid],fmaf(oz,W1[512+tid],b1[tid])));
    s_c[2*tid+1]=fmaf(dx,W1[tid],fmaf(dy,W1[256+tid],dz*W1[512+tid]));
    __syncthreads();
    {
        int m=tid&127, kh=tid>>7;
        float d=a+(float)m*st;
#pragma unroll 4
        for(int j=0;j<128;j+=2){
            int k=kh*128+j;
            float2 ca=*(float2*)(s_c+2*k);
            float2 cb=*(float2*)(s_c+2*k+2);
            float v0=softplusf(fmaf(d,ca.y,ca.x));
            float v1=softplusf(fmaf(d,cb.y,cb.x));
            int off=m*512+((((k>>3))^(m&7))<<4)+((k&7)<<1);
            *(u32*)(sm+ABH+off)=pkbf(v0,v1);
        }
    }

    int g2=lane>>3, row=lane&7;
    int mw=warp&1, nw=warp>>1;
    int n0=nw*64;
    u32 boff=(u32)((n0+(g2>>1)*8+row)*48+(g2&1)*16);

    for(int L=0;L<2;L++){
        __syncthreads();
        s_bias[tid]=L?b3[tid]:b2[tid];
        if(L) s_w4[tid]=W4[tid];
        const unsigned char* blobH=g_WB[L][0];
        for(int mh=0;mh<2;mh++){
            int m0=mh*64+mw*32;
            u32 arow=(u32)((m0+(g2&1)*8+row)*512);
            float acc[2][8][4];
#pragma unroll
            for(int i=0;i<2;i++)
#pragma unroll
                for(int j=0;j<8;j++){ acc[i][j][0]=0.f; acc[i][j][1]=0.f; acc[i][j][2]=0.f; acc[i][j][3]=0.f; }
            if(!(L==0&&mh==0)){
                stageBh(sm+BBF,blobH,tid); cp_commit();
                stageBh(sm+BBF+12288,blobH+12288,tid); cp_commit();
            }
            for(int c=0;c<16;c++){
                if(c<14) cp_wait1(); else cp_wait0();
                __syncthreads();
                if(c<14){ stageBh(sm+BBF+((c+2)%3)*12288,blobH+(c+2)*12288,tid); cp_commit(); }
                u32 bb=smb+BBF+(c%3)*12288;
                u32 bh[4][4];
#pragma unroll
                for(int j=0;j<4;j++) ldm4(bh[j],bb+boff+j*768);
                u32 au=(u32)(((2*c+(g2>>1))^row)<<4);
                u32 ah[2][4];
                ldm4(ah[0],smb+ABH+arow+au);
                ldm4(ah[1],smb+ABH+arow+8192u+au);
#pragma unroll
                for(int mt=0;mt<2;mt++)
#pragma unroll
                    for(int nt=0;nt<8;nt++){
                        const u32* B=bh[nt>>1];
                        mma16816(acc[mt][nt],ah[mt],B[(nt&1)*2],B[(nt&1)*2+1]);
                    }
            }
            __syncthreads();
            if(L==0){
#pragma unroll
                for(int mt=0;mt<2;mt++){
                    int r0=m0+mt*16+(lane>>2), r1=r0+8;
#pragma unroll
                    for(int nt=0;nt<8;nt++){
                        int n=n0+nt*8+(lane&3)*2;
                        float v0=softplusf(acc[mt][nt][0]+s_bias[n]);
                        float v1=softplusf(acc[mt][nt][1]+s_bias[n+1]);
                        float v2=softplusf(acc[mt][nt][2]+s_bias[n]);
                        float v3=softplusf(acc[mt][nt][3]+s_bias[n+1]);
                        int o0=r0*512+(((n>>3)^(r0&7))<<4)+(n&7)*2;
                        int o1=r1*512+(((n>>3)^(r1&7))<<4)+(n&7)*2;
                        *(u32*)(sm+ABH+o0)=pkbf(v0,v1);
                        *(u32*)(sm+ABH+o1)=pkbf(v2,v3);
                    }
                }
            } else {
#pragma unroll
                for(int mt=0;mt<2;mt++){
                    float s0=0.f,s1=0.f;
#pragma unroll
                    for(int nt=0;nt<8;nt++){
                        int n=n0+nt*8+(lane&3)*2;
                        s0+=softplusf(acc[mt][nt][0]+s_bias[n])*s_w4[n]
                           +softplusf(acc[mt][nt][1]+s_bias[n+1])*s_w4[n+1];
                        s1+=softplusf(acc[mt][nt][2]+s_bias[n])*s_w4[n]
                           +softplusf(acc[mt][nt][3]+s_bias[n+1])*s_w4[n+1];
                    }
                    s0+=__shfl_xor_sync(0xffffffffu,s0,1); s0+=__shfl_xor_sync(0xffffffffu,s0,2);
                    s1+=__shfl_xor_sync(0xffffffffu,s1,1); s1+=__shfl_xor_sync(0xffffffffu,s1,2);
                    if((lane&3)==0){
                        int r0=m0+mt*16+(lane>>2);
                        s_red[r0*4+nw]=s0;
                        s_red[(r0+8)*4+nw]=s1;
                    }
                }
            }
        }
    }
    __syncthreads();
    if(tid<128)
        g_val[ray*SSAMP+tid]=s_red[tid*4]+s_red[tid*4+1]+s_red[tid*4+2]+s_red[tid*4+3]+b4[0];
}

// ======== k_refine: HMMA evals, M=64; NP=1 secant (3-deep pipe), NP=3 finals ========
#define RBH 0
#define RBL 32768
#define RBB 65536   // NP3: 2 x 24576 ; NP1: 3 x 12288
template<int NP>
__device__ __forceinline__ void eval_mma(char* sm,u32 smb,int tid,float delta,
    const float* __restrict__ W1,const float* __restrict__ b1,
    const float* s_o,const float* s_rd,const float* s_dp,
    const float* s_bias2,const float* s_bias3,const float* s_w4,float b4v,
    float* s_red,float* s_f){
    int lane=tid&31, warp=tid>>5;
    {
        int m=tid&63, kg=tid>>6;
        float d=s_dp[m]+delta;
        float px=s_o[m]+d*s_rd[m], py=s_o[64+m]+d*s_rd[64+m], pz=s_o[128+m]+d*s_rd[128+m];
#pragma unroll 4
        for(int j=0;j<64;j+=2){
            int k=kg*64+j;
            float z0=fmaf(px,W1[k],fmaf(py,W1[256+k],fmaf(pz,W1[512+k],b1[k])));
            float z1=fmaf(px,W1[k+1],fmaf(py,W1[257+k],fmaf(pz,W1[513+k],b1[k+1])));
            float v0=softplusf(z0), v1=softplusf(z1);
            int off=m*512+((((k>>3))^(m&7))<<4)+((k&7)<<1);
            if(NP==3){
                u32 h,l; splitpk(v0,v1,h,l);
                *(u32*)(sm+RBH+off)=h;
                *(u32*)(sm+RBL+off)=l;
            } else {
                *(u32*)(sm+RBH+off)=pkbf(v0,v1);
            }
        }
    }
    int g2=lane>>3, row=lane&7;
    int mw=warp&1, nw=warp>>1;
    int m0=mw*32, n0=nw*64;
    u32 arow=(u32)((m0+(g2&1)*8+row)*512);
    u32 boff=(u32)((n0+(g2>>1)*8+row)*48+(g2&1)*16);

    for(int L=0;L<2;L++){
        const float* bias=L?s_bias3:s_bias2;
        const unsigned char* blobH=g_WB[L][0];
        const unsigned char* blobL=g_WB[L][1];
        float acc[2][8][4];
#pragma unroll
        for(int i=0;i<2;i++)
#pragma unroll
            for(int j=0;j<8;j++){ acc[i][j][0]=0.f; acc[i][j][1]=0.f; acc[i][j][2]=0.f; acc[i][j][3]=0.f; }
        if(NP==3){
            stageB(sm+RBB,blobH,blobL,tid); cp_commit();
        } else {
            stageBh(sm+RBB,blobH,tid); cp_commit();
            stageBh(sm+RBB+12288,blobH+12288,tid); cp_commit();
        }
        for(int c=0;c<16;c++){
            if(NP==3){
                cp_wait0();
            } else {
                if(c<14) cp_wait1(); else cp_wait0();
            }
            __syncthreads();
            if(NP==3){
                if(c<15){ stageB(sm+RBB+((c+1)&1)*24576,blobH+(c+1)*12288,blobL+(c+1)*12288,tid); cp_commit(); }
            } else {
                if(c<14){ stageBh(sm+RBB+((c+2)%3)*12288,blobH+(c+2)*12288,tid); cp_commit(); }
            }
            u32 bb=(NP==3)?(smb+RBB+(c&1)*24576):(smb+RBB+(c%3)*12288);
            u32 bh[4][4], bl[4][4];
#pragma unroll
            for(int j=0;j<4;j++){
                u32 ba=bb+boff+j*768;
                ldm4(bh[j],ba);
                if(NP==3) ldm4(bl[j],ba+12288);
            }
            u32 au=(u32)(((2*c+(g2>>1))^row)<<4);
            u32 ah[2][4], al[2][4];
            ldm4(ah[0],smb+RBH+arow+au);
            ldm4(ah[1],smb+RBH+arow+8192u+au);
            if(NP==3){
                ldm4(al[0],smb+RBL+arow+au);
                ldm4(al[1],smb+RBL+arow+8192u+au);
            }
#pragma unroll
            for(int mt=0;mt<2;mt++){
#pragma unroll
                for(int p=0;p<NP;p++){
                    const u32* A=(p==2)?al[mt]:ah[mt];
#pragma unroll
                    for(int nt=0;nt<8;nt++){
                        const u32* B=(p==1)?bl[nt>>1]:bh[nt>>1];
                        mma16816(acc[mt][nt],A,B[(nt&1)*2],B[(nt&1)*2+1]);
                    }
                }
            }
        }
        __syncthreads();
        if(L==0){
#pragma unroll
            for(int mt=0;mt<2;mt++){
                int r0=m0+mt*16+(lane>>2), r1=r0+8;
#pragma unroll
                for(int nt=0;nt<8;nt++){
                    int n=n0+nt*8+(lane&3)*2;
                    float v0=softplusf(acc[mt][nt][0]+bias[n]);
                    float v1=softplusf(acc[mt][nt][1]+bias[n+1]);
                    float v2=softplusf(acc[mt][nt][2]+bias[n]);
                    float v3=softplusf(acc[mt][nt][3]+bias[n+1]);
                    int o0=r0*512+(((n>>3)^(r0&7))<<4)+(n&7)*2;
                    int o1=r1*512+(((n>>3)^(r1&7))<<4)+(n&7)*2;
                    if(NP==3){
                        u32 h0,l0,h1,l1;
                        splitpk(v0,v1,h0,l0);
                        splitpk(v2,v3,h1,l1);
                        *(u32*)(sm+RBH+o0)=h0; *(u32*)(sm+RBL+o0)=l0;
                        *(u32*)(sm+RBH+o1)=h1; *(u32*)(sm+RBL+o1)=l1;
                    } else {
                        *(u32*)(sm+RBH+o0)=pkbf(v0,v1);
                        *(u32*)(sm+RBH+o1)=pkbf(v2,v3);
                    }
                }
            }
        } else {
#pragma unroll
            for(int mt=0;mt<2;mt++){
                float s0=0.f,s1=0.f;
#pragma unroll
                for(int nt=0;nt<8;nt++){
                    int n=n0+nt*8+(lane&3)*2;
                    s0+=softplusf(acc[mt][nt][0]+bias[n])*s_w4[n]
                       +softplusf(acc[mt][nt][1]+bias[n+1])*s_w4[n+1];
                    s1+=softplusf(acc[mt][nt][2]+bias[n])*s_w4[n]
                       +softplusf(acc[mt][nt][3]+bias[n+1])*s_w4[n+1];
                }
                s0+=__shfl_xor_sync(0xffffffffu,s0,1); s0+=__shfl_xor_sync(0xffffffffu,s0,2);
                s1+=__shfl_xor_sync(0xffffffffu,s1,1); s1+=__shfl_xor_sync(0xffffffffu,s1,2);
                if((lane&3)==0){
                    int r0=m0+mt*16+(lane>>2);
                    s_red[r0*4+nw]=s0;
                    s_red[(r0+8)*4+nw]=s1;
                }
            }
            __syncthreads();
            if(tid<64) s_f[tid]=s_red[tid*4]+s_red[tid*4+1]+s_red[tid*4+2]+s_red[tid*4+3]+b4v;
        }
        __syncthreads();
    }
}

__global__ void __launch_bounds__(256,1)
k_refine(const float* __restrict__ ray0,const float* __restrict__ rdir,
         const float* __restrict__ W1,const float* __restrict__ b1,
         const float* __restrict__ b2,const float* __restrict__ b3,
         const float* __restrict__ W4,const float* __restrict__ b4,
         float* __restrict__ out){
    extern __shared__ char sm[];
    __shared__ float s_bias2[256],s_bias3[256],s_w4[256],s_red[256];
    __shared__ float s_o[192],s_rd[192];
    __shared__ float s_dl[64],s_fl[64],s_dh[64],s_fh[64],s_dp[64],s_f[64],s_f0[64],s_fm[64];
    __shared__ float s_a[64],s_b[64];
    __shared__ int s_mask[64];
    int tid=threadIdx.x, rbase=blockIdx.x*64;
    u32 smb=smem_u32(sm);
    s_bias2[tid]=b2[tid]; s_bias3[tid]=b3[tid]; s_w4[tid]=W4[tid];
    float b4v=b4[0];
    if(tid<64){
        int r=rbase+tid;
        s_o[tid]=ray0[3*r]; s_o[64+tid]=ray0[3*r+1]; s_o[128+tid]=ray0[3*r+2];
        s_rd[tid]=rdir[3*r]; s_rd[64+tid]=rdir[3*r+1]; s_rd[128+tid]=rdir[3*r+2];
        s_a[tid]=g_a[r]; s_b[tid]=g_b[r];
    }
    float* vbuf=(float*)sm;
    for(int i=tid;i<64*SSAMP;i+=256) vbuf[i]=g_val[rbase*SSAMP+i];
    __syncthreads();
    if(tid<64){
        const float* v=vbuf+tid*SSAMP;
        float best=1e30f; int bidx=0;
        for(int s=0;s<SSAMP;s++){
            float c;
            if(s<SSAMP-1){ float pr=v[s]*v[s+1];
                float sg=(pr>0.f)?1.f:((pr<0.f)?-1.f:0.f); c=sg*(float)(SSAMP-s); }
            else c=1.f;
            if(c<best){ best=c; bidx=s; }
        }
        float fl=v[bidx];
        int ihi=bidx+1; if(ihi>SSAMP-1) ihi=SSAMP-1;
        float dl=s_a[tid]+(float)bidx*s_b[tid];
        float dh=s_a[tid]+(float)ihi*s_b[tid];
        float fh=v[ihi];
        s_mask[tid]=(best<0.f)&&(fl<0.f)&&(v[0]<0.f);
        s_dl[tid]=dl; s_fl[tid]=fl; s_dh[tid]=dh; s_fh[tid]=fh;
        s_dp[tid]=secantf(dl,fl,dh,fh);
    }
    __syncthreads();
    for(int it=0;it<8;it++){
        eval_mma<1>(sm,smb,tid,0.f,W1,b1,s_o,s_rd,s_dp,s_bias2,s_bias3,s_w4,b4v,s_red,s_f);
        if(tid<64){
            float fm=s_f[tid];
            float dl=s_dl[tid],fl=s_fl[tid],dh=s_dh[tid],fh=s_fh[tid],dp=s_dp[tid];
            if(fm<0.f){ dl=dp; fl=fm; } else { dh=dp; fh=fm; }
            s_dl[tid]=dl; s_fl[tid]=fl; s_dh[tid]=dh; s_fh[tid]=fh;
            s_dp[tid]=secantf(dl,fl,dh,fh);
        }
        __syncthreads();
    }
    eval_mma<3>(sm,smb,tid,0.f,W1,b1,s_o,s_rd,s_dp,s_bias2,s_bias3,s_w4,b4v,s_red,s_f);
    if(tid<64) s_f0[tid]=s_f[tid];
    __syncthreads();
    eval_mma<3>(sm,smb,tid,-FDE,W1,b1,s_o,s_rd,s_dp,s_bias2,s_bias3,s_w4,b4v,s_red,s_f);
    if(tid<64) s_fm[tid]=s_f[tid];
    __syncthreads();
    eval_mma<3>(sm,smb,tid,FDE,W1,b1,s_o,s_rd,s_dp,s_bias2,s_bias3,s_w4,b4v,s_red,s_f);
    if(tid<64){
        float df=(s_f[tid]-s_fm[tid])*(0.5f/FDE);
        if(fabsf(df)<1e-6f) df=(df<0.f)?-1e-6f:1e-6f;
        float dout=s_dp[tid]-s_f0[tid]/df;
        out[rbase+tid]=s_mask[tid]?dout:0.f;
    }
}

extern "C" void kernel_launch(void* const* d_in,const int* in_sizes,int n_in,
                              void* d_out,int out_size){
    const float* ray0=(const float*)d_in[0];
    const float* rdir=(const float*)d_in[1];
    const float* W1=(const float*)d_in[2];
    const float* b1=(const float*)d_in[3];
    const float* W2=(const float*)d_in[4];
    const float* b2=(const float*)d_in[5];
    const float* W3=(const float*)d_in[6];
    const float* b3=(const float*)d_in[7];
    const float* W4=(const float*)d_in[8];
    const float* b4=(const float*)d_in[9];
    float* out=(float*)d_out;
    const int smemBig=102400;
    const int smemRef=114688;
    cudaFuncSetAttribute(k_big,cudaFuncAttributeMaxDynamicSharedMemorySize,smemBig);
    cudaFuncSetAttribute(k_refine,cudaFuncAttributeMaxDynamicSharedMemorySize,smemRef);
    k_prep<<<512,256>>>(W2,W3);
    k_setup<<<(NRAYS+255)/256,256>>>(ray0,rdir);
    k_big<<<NRAYS,256,smemBig>>>(ray0,rdir,W1,b1,b2,b3,W4,b4);
    k_refine<<<NRAYS/64,256,smemRef>>>(ray0,rdir,W1,b1,b2,b3,W4,b4,out);
}